// round 1
// baseline (speedup 1.0000x reference)
#include <cuda_runtime.h>
#include <cuda_bf16.h>
#include <math.h>

#define T_SEQ 2048
#define NH 16
#define HD 64
#define NE 1024
#define KVW 512   // 8 octonion groups * 64 (p,q) outer-product entries

// ---------------- scratch (static device globals; no runtime allocation) ----
__device__ float g_qraw[(size_t)T_SEQ * NE];
__device__ float g_kraw[(size_t)T_SEQ * NE];
__device__ float g_vraw[(size_t)T_SEQ * NE];
__device__ float g_qh[(size_t)NH * T_SEQ * HD];
__device__ float g_kh[(size_t)NH * T_SEQ * HD];
__device__ float g_kv[(size_t)NH * T_SEQ * KVW];
__device__ float g_att[(size_t)NH * T_SEQ * T_SEQ];
__device__ float g_z[(size_t)NH * T_SEQ * KVW];
__device__ float g_ypre[(size_t)T_SEQ * NE];

// ---------------- octonion helpers (all compile-time foldable) --------------
__device__ __forceinline__ void qmul_d(const float* a, const float* b, float* r) {
    r[0] = a[0]*b[0] - a[1]*b[1] - a[2]*b[2] - a[3]*b[3];
    r[1] = a[0]*b[1] + a[1]*b[0] + a[2]*b[3] - a[3]*b[2];
    r[2] = a[0]*b[2] - a[1]*b[3] + a[2]*b[0] + a[3]*b[1];
    r[3] = a[0]*b[3] + a[1]*b[2] - a[2]*b[1] + a[3]*b[0];
}

// Cayley-Dickson octonion product: (a,b)*(c,d) = (ac - d̄b, da + bc̄)
__device__ __forceinline__ void omul_d(const float* x, const float* y, float* r) {
    float a[4] = {x[0], x[1], x[2], x[3]};
    float b[4] = {x[4], x[5], x[6], x[7]};
    float c[4] = {y[0], y[1], y[2], y[3]};
    float d[4] = {y[4], y[5], y[6], y[7]};
    float dc[4] = { d[0], -d[1], -d[2], -d[3] };   // qconj(d)
    float cc[4] = { c[0], -c[1], -c[2], -c[3] };   // qconj(c)
    float t1[4], t2[4], t3[4], t4[4];
    qmul_d(a,  c,  t1);
    qmul_d(dc, b,  t2);
    qmul_d(d,  a,  t3);
    qmul_d(b,  cc, t4);
    #pragma unroll
    for (int i = 0; i < 4; i++) { r[i]   = t1[i] - t2[i]; }
    #pragma unroll
    for (int i = 0; i < 4; i++) { r[4+i] = t3[i] + t4[i]; }
}

// ---------------- generic tiled SGEMM: C[M,N] = A[M,K] * B[N,K]^T -----------
// BM=BN=64, BK=16, 256 threads, 4x4 per thread
__global__ __launch_bounds__(256) void gemm_nt(
    const float* __restrict__ A, const float* __restrict__ B,
    float* __restrict__ C, int M, int N, int K)
{
    __shared__ float As[16][64];
    __shared__ float Bs[16][64];
    const int m0 = blockIdx.y * 64;
    const int n0 = blockIdx.x * 64;
    const int tid = threadIdx.x;
    const int tx = tid & 15, ty = tid >> 4;
    const int lr = tid >> 2;          // 0..63 row within tile
    const int lc = (tid & 3) * 4;     // k offset (0,4,8,12)
    float acc[4][4] = {};

    for (int k0 = 0; k0 < K; k0 += 16) {
        float4 av = *(const float4*)&A[(size_t)(m0 + lr) * K + k0 + lc];
        float4 bv = *(const float4*)&B[(size_t)(n0 + lr) * K + k0 + lc];
        As[lc+0][lr] = av.x; As[lc+1][lr] = av.y; As[lc+2][lr] = av.z; As[lc+3][lr] = av.w;
        Bs[lc+0][lr] = bv.x; Bs[lc+1][lr] = bv.y; Bs[lc+2][lr] = bv.z; Bs[lc+3][lr] = bv.w;
        __syncthreads();
        #pragma unroll
        for (int kk = 0; kk < 16; kk++) {
            float4 a = *(const float4*)&As[kk][ty * 4];
            float4 b = *(const float4*)&Bs[kk][tx * 4];
            float ar[4] = {a.x, a.y, a.z, a.w};
            float br[4] = {b.x, b.y, b.z, b.w};
            #pragma unroll
            for (int i = 0; i < 4; i++) {
                #pragma unroll
                for (int j = 0; j < 4; j++) acc[i][j] += ar[i] * br[j];
            }
        }
        __syncthreads();
    }
    #pragma unroll
    for (int i = 0; i < 4; i++) {
        float4 v = make_float4(acc[i][0], acc[i][1], acc[i][2], acc[i][3]);
        *(float4*)&C[(size_t)(m0 + ty * 4 + i) * N + n0 + tx * 4] = v;
    }
}

// ---------------- fused RoPE + RMS + octonion conj-unit + KV outer ----------
// grid: T_SEQ blocks, 512 threads (16 warps = 16 heads, 1 warp per head)
__global__ __launch_bounds__(512) void rope_rms_kv(
    const float* __restrict__ qraw, const float* __restrict__ kraw,
    const float* __restrict__ vraw, const float* __restrict__ cosb,
    const float* __restrict__ sinb,
    float* __restrict__ qh, float* __restrict__ kh, float* __restrict__ kv)
{
    const int t = blockIdx.x;
    const int h = threadIdx.x >> 5;
    const int lane = threadIdx.x & 31;
    const unsigned FULL = 0xffffffffu;

    const float c = cosb[t * 32 + lane];
    const float s = sinb[t * 32 + lane];
    const size_t base = (size_t)t * NE + (size_t)h * HD;
    float q1 = qraw[base + lane], q2 = qraw[base + lane + 32];
    float k1 = kraw[base + lane], k2 = kraw[base + lane + 32];
    float v1 = vraw[base + lane], v2 = vraw[base + lane + 32];

    // rotary: x1*c + x2*s ; x2*c - x1*s
    float qr1 = q1 * c + q2 * s, qr2 = q2 * c - q1 * s;
    float kr1 = k1 * c + k2 * s, kr2 = k2 * c - k1 * s;

    // RMS over 64 dims (warp allreduce)
    float sq = qr1 * qr1 + qr2 * qr2;
    float sk = kr1 * kr1 + kr2 * kr2;
    #pragma unroll
    for (int off = 16; off > 0; off >>= 1) {
        sq += __shfl_xor_sync(FULL, sq, off);
        sk += __shfl_xor_sync(FULL, sk, off);
    }
    const float rq = rsqrtf(sq * (1.0f / 64.0f) + 1e-6f);
    const float rk = rsqrtf(sk * (1.0f / 64.0f) + 1e-6f);
    qr1 *= rq; qr2 *= rq;
    kr1 *= rk; kr2 *= rk;

    const size_t hb = ((size_t)h * T_SEQ + t) * HD;
    qh[hb + lane] = qr1; qh[hb + lane + 32] = qr2;
    kh[hb + lane] = kr1; kh[hb + lane + 32] = kr2;

    // octonion group norms (aligned 8-lane segments) -> unit + conj
    float g1 = kr1 * kr1, g2 = kr2 * kr2;
    #pragma unroll
    for (int off = 1; off < 8; off <<= 1) {
        g1 += __shfl_xor_sync(FULL, g1, off);
        g2 += __shfl_xor_sync(FULL, g2, off);
    }
    const float sgn = ((lane & 7) == 0) ? 1.0f : -1.0f;  // oconj: + only comp 0
    const float kc1 = sgn * kr1 / fmaxf(sqrtf(g1), 1e-12f);
    const float kc2 = sgn * kr2 / fmaxf(sqrtf(g2), 1e-12f);

    __shared__ float skc[16][64];
    __shared__ float sv[16][64];
    skc[h][lane] = kc1; skc[h][lane + 32] = kc2;
    sv[h][lane]  = v1;  sv[h][lane + 32]  = v2;
    __syncwarp();

    // KV[j, m, p, q] = kc[m*8+p] * v[m*8+q]
    float* kvrow = kv + ((size_t)h * T_SEQ + t) * KVW;
    #pragma unroll
    for (int r = 0; r < 16; r++) {
        int n = lane + 32 * r;
        int m = n >> 6, p = (n >> 3) & 7, q = n & 7;
        kvrow[n] = skc[h][m * 8 + p] * sv[h][m * 8 + q];
    }
}

// ---------------- scores GEMM (per head, causal block-skip, *1/8) -----------
__global__ __launch_bounds__(256) void scores_gemm(
    const float* __restrict__ qh, const float* __restrict__ kh,
    float* __restrict__ att)
{
    const int h = blockIdx.z;
    const int m0 = blockIdx.y * 64;
    const int n0 = blockIdx.x * 64;
    if (n0 > m0 + 63) return;  // fully above diagonal: never read
    const float* A = qh + (size_t)h * T_SEQ * HD;
    const float* B = kh + (size_t)h * T_SEQ * HD;
    float* C = att + (size_t)h * T_SEQ * T_SEQ;

    __shared__ float As[16][64];
    __shared__ float Bs[16][64];
    const int tid = threadIdx.x;
    const int tx = tid & 15, ty = tid >> 4;
    const int lr = tid >> 2;
    const int lc = (tid & 3) * 4;
    float acc[4][4] = {};

    for (int k0 = 0; k0 < HD; k0 += 16) {
        float4 av = *(const float4*)&A[(size_t)(m0 + lr) * HD + k0 + lc];
        float4 bv = *(const float4*)&B[(size_t)(n0 + lr) * HD + k0 + lc];
        As[lc+0][lr] = av.x; As[lc+1][lr] = av.y; As[lc+2][lr] = av.z; As[lc+3][lr] = av.w;
        Bs[lc+0][lr] = bv.x; Bs[lc+1][lr] = bv.y; Bs[lc+2][lr] = bv.z; Bs[lc+3][lr] = bv.w;
        __syncthreads();
        #pragma unroll
        for (int kk = 0; kk < 16; kk++) {
            float4 a = *(const float4*)&As[kk][ty * 4];
            float4 b = *(const float4*)&Bs[kk][tx * 4];
            float ar[4] = {a.x, a.y, a.z, a.w};
            float br[4] = {b.x, b.y, b.z, b.w};
            #pragma unroll
            for (int i = 0; i < 4; i++) {
                #pragma unroll
                for (int j = 0; j < 4; j++) acc[i][j] += ar[i] * br[j];
            }
        }
        __syncthreads();
    }
    #pragma unroll
    for (int i = 0; i < 4; i++) {
        float4 v = make_float4(acc[i][0] * 0.125f, acc[i][1] * 0.125f,
                               acc[i][2] * 0.125f, acc[i][3] * 0.125f);
        *(float4*)&C[(size_t)(m0 + ty * 4 + i) * T_SEQ + n0 + tx * 4] = v;
    }
}

// ---------------- softmax rows (in-place, causal length i+1) ----------------
__global__ __launch_bounds__(256) void softmax_rows(float* __restrict__ att)
{
    const int i = blockIdx.x;
    const int h = blockIdx.y;
    float* row = att + (size_t)h * T_SEQ * T_SEQ + (size_t)i * T_SEQ;
    const int n = i + 1;
    const int tid = threadIdx.x;

    float v[8];
    int cnt = 0;
    float mx = -1e30f;
    for (int j = tid; j < n; j += 256) {
        float x = row[j];
        v[cnt++] = x;
        mx = fmaxf(mx, x);
    }
    __shared__ float red[256];
    red[tid] = mx; __syncthreads();
    #pragma unroll
    for (int s = 128; s > 0; s >>= 1) {
        if (tid < s) red[tid] = fmaxf(red[tid], red[tid + s]);
        __syncthreads();
    }
    mx = red[0]; __syncthreads();

    float sum = 0.0f;
    for (int c2 = 0; c2 < cnt; c2++) { v[c2] = __expf(v[c2] - mx); sum += v[c2]; }
    red[tid] = sum; __syncthreads();
    #pragma unroll
    for (int s = 128; s > 0; s >>= 1) {
        if (tid < s) red[tid] += red[tid + s];
        __syncthreads();
    }
    const float inv = 1.0f / red[0];
    cnt = 0;
    for (int j = tid; j < n; j += 256) row[j] = v[cnt++] * inv;
}

// ---------------- Z GEMM: z[h] = att[h] @ kv[h] (causal K-truncation) -------
// C[M=2048, N=512] = A[M, K=2048] * B[K, N]; A masked to j<=i.
__global__ __launch_bounds__(256) void z_gemm(
    const float* __restrict__ att, const float* __restrict__ kv,
    float* __restrict__ z)
{
    const int h = blockIdx.z;
    const int m0 = blockIdx.y * 64;
    const int n0 = blockIdx.x * 64;
    const float* A = att + (size_t)h * T_SEQ * T_SEQ;
    const float* B = kv + (size_t)h * T_SEQ * KVW;
    float* C = z + (size_t)h * T_SEQ * KVW;

    __shared__ float As[16][64];
    __shared__ float Bs[16][64];
    const int tid = threadIdx.x;
    const int tx = tid & 15, ty = tid >> 4;
    const int lr = tid >> 2;
    const int lc = (tid & 3) * 4;
    const int brow = tid >> 4;           // 0..15
    const int bcol = (tid & 15) * 4;     // 0..60
    float acc[4][4] = {};

    const int kend = m0 + 64;  // only j <= i_max needed
    for (int k0 = 0; k0 < kend; k0 += 16) {
        const int ig = m0 + lr;
        const int jb = k0 + lc;
        const float* ap = &A[(size_t)ig * T_SEQ + jb];
        As[lc+0][lr] = (jb + 0 <= ig) ? ap[0] : 0.0f;
        As[lc+1][lr] = (jb + 1 <= ig) ? ap[1] : 0.0f;
        As[lc+2][lr] = (jb + 2 <= ig) ? ap[2] : 0.0f;
        As[lc+3][lr] = (jb + 3 <= ig) ? ap[3] : 0.0f;
        float4 bv = *(const float4*)&B[(size_t)(k0 + brow) * KVW + n0 + bcol];
        *(float4*)&Bs[brow][bcol] = bv;
        __syncthreads();
        #pragma unroll
        for (int kk = 0; kk < 16; kk++) {
            float4 a = *(const float4*)&As[kk][ty * 4];
            float4 b = *(const float4*)&Bs[kk][tx * 4];
            float ar[4] = {a.x, a.y, a.z, a.w};
            float br[4] = {b.x, b.y, b.z, b.w};
            #pragma unroll
            for (int i = 0; i < 4; i++) {
                #pragma unroll
                for (int j = 0; j < 4; j++) acc[i][j] += ar[i] * br[j];
            }
        }
        __syncthreads();
    }
    #pragma unroll
    for (int i = 0; i < 4; i++) {
        float4 v = make_float4(acc[i][0], acc[i][1], acc[i][2], acc[i][3]);
        *(float4*)&C[(size_t)(m0 + ty * 4 + i) * KVW + n0 + tx * 4] = v;
    }
}

// ---------------- final octonion contraction: y = sum_p (u o e_p) o Z_p -----
// one thread per (t, h, m); 2048*16*8 = 262144 threads
__global__ __launch_bounds__(256) void y_contract(
    const float* __restrict__ qh, const float* __restrict__ z,
    float* __restrict__ ypre)
{
    const int gid = blockIdx.x * blockDim.x + threadIdx.x;
    const int t = gid >> 7;
    const int r = gid & 127;
    const int h = r >> 3;
    const int m = r & 7;

    const float* u_ptr = qh + ((size_t)h * T_SEQ + t) * HD + m * 8;
    const float* zr = z + ((size_t)h * T_SEQ + t) * KVW + m * 64;

    float u[8];
    #pragma unroll
    for (int i = 0; i < 8; i++) u[i] = u_ptr[i];

    float y[8] = {};
    #pragma unroll
    for (int p = 0; p < 8; p++) {
        float ep[8] = {};
        ep[p] = 1.0f;                 // p is compile-time constant after unroll
        float w[8];
        omul_d(u, ep, w);             // folds to signed permutation
        float zp[8];
        #pragma unroll
        for (int q = 0; q < 8; q++) zp[q] = zr[p * 8 + q];
        float tt[8];
        omul_d(w, zp, tt);
        #pragma unroll
        for (int k = 0; k < 8; k++) y[k] += tt[k];
    }
    float* out = ypre + (size_t)t * NE + h * 64 + m * 8;
    #pragma unroll
    for (int k = 0; k < 8; k++) out[k] = y[k];
}

// ---------------- launch --------------------------------------------------
extern "C" void kernel_launch(void* const* d_in, const int* in_sizes, int n_in,
                              void* d_out, int out_size)
{
    const float* x    = (const float*)d_in[0];
    const float* cosb = (const float*)d_in[1];
    const float* sinb = (const float*)d_in[2];
    const float* Wq   = (const float*)d_in[3];
    const float* Wk   = (const float*)d_in[4];
    const float* Wv   = (const float*)d_in[5];
    const float* Wo   = (const float*)d_in[6];
    float* out = (float*)d_out;

    float *qraw, *kraw, *vraw, *qh, *kh, *kv, *att, *z, *ypre;
    cudaGetSymbolAddress((void**)&qraw, g_qraw);
    cudaGetSymbolAddress((void**)&kraw, g_kraw);
    cudaGetSymbolAddress((void**)&vraw, g_vraw);
    cudaGetSymbolAddress((void**)&qh,   g_qh);
    cudaGetSymbolAddress((void**)&kh,   g_kh);
    cudaGetSymbolAddress((void**)&kv,   g_kv);
    cudaGetSymbolAddress((void**)&att,  g_att);
    cudaGetSymbolAddress((void**)&z,    g_z);
    cudaGetSymbolAddress((void**)&ypre, g_ypre);

    // 1-3: QKV projections
    dim3 gproj(NE / 64, T_SEQ / 64);
    gemm_nt<<<gproj, 256>>>(x, Wq, qraw, T_SEQ, NE, NE);
    gemm_nt<<<gproj, 256>>>(x, Wk, kraw, T_SEQ, NE, NE);
    gemm_nt<<<gproj, 256>>>(x, Wv, vraw, T_SEQ, NE, NE);

    // 4: rope + rms + octonion conj/unit + KV outer products
    rope_rms_kv<<<T_SEQ, 512>>>(qraw, kraw, vraw, cosb, sinb, qh, kh, kv);

    // 5: scores (causal blocks only)
    dim3 gsc(T_SEQ / 64, T_SEQ / 64, NH);
    scores_gemm<<<gsc, 256>>>(qh, kh, att);

    // 6: softmax
    softmax_rows<<<dim3(T_SEQ, NH), 256>>>(att);

    // 7: Z = probs @ KV (causal)
    dim3 gz(KVW / 64, T_SEQ / 64, NH);
    z_gemm<<<gz, 256>>>(att, kv, z);

    // 8: octonion contraction -> ypre [T, NE]
    y_contract<<<(T_SEQ * NH * 8) / 256, 256>>>(qh, z, ypre);

    // 9: output projection
    gemm_nt<<<gproj, 256>>>(ypre, Wo, out, T_SEQ, NE, NE);
}

// round 7
// speedup vs baseline: 1.3380x; 1.3380x over previous
#include <cuda_runtime.h>
#include <cuda_bf16.h>
#include <math.h>

#define T_SEQ 2048
#define NH 16
#define HD 64
#define NE 1024
#define KVW 512   // 8 octonion groups * 64 (p,q) outer-product entries

// ---------------- scratch (static device globals; no runtime allocation) ----
__device__ float g_qraw[(size_t)T_SEQ * NE];
__device__ float g_kraw[(size_t)T_SEQ * NE];
__device__ float g_vraw[(size_t)T_SEQ * NE];
__device__ float g_qh[(size_t)NH * T_SEQ * HD];
__device__ float g_kh[(size_t)NH * T_SEQ * HD];
__device__ float g_kv[(size_t)NH * T_SEQ * KVW];
__device__ float g_att[(size_t)NH * T_SEQ * T_SEQ];
__device__ float g_z[(size_t)NH * T_SEQ * KVW];
__device__ float g_ypre[(size_t)T_SEQ * NE];

// ---------------- async copy helpers ---------------------------------------
__device__ __forceinline__ unsigned smem_u32(const void* p) {
    return (unsigned)__cvta_generic_to_shared(p);
}
#define CPA16(dst_u32, src_ptr) \
    asm volatile("cp.async.cg.shared.global [%0], [%1], 16;" :: "r"(dst_u32), "l"(src_ptr))
#define CPCOMMIT() asm volatile("cp.async.commit_group;")
#define CPWAIT1()  asm volatile("cp.async.wait_group 1;")
#define CPWAIT0()  asm volatile("cp.async.wait_group 0;")

// bf16 warp MMA: D(16x8) += A(16x16) * B(16x8)
__device__ __forceinline__ void mma16(float* d, const unsigned* a, const unsigned* b) {
    asm volatile(
        "mma.sync.aligned.m16n8k16.row.col.f32.bf16.bf16.f32 "
        "{%0,%1,%2,%3},{%4,%5,%6,%7},{%8,%9},{%0,%1,%2,%3};"
        : "+f"(d[0]), "+f"(d[1]), "+f"(d[2]), "+f"(d[3])
        : "r"(a[0]), "r"(a[1]), "r"(a[2]), "r"(a[3]), "r"(b[0]), "r"(b[1]));
}

// split two fp32 into packed bf16 hi + bf16 residual lo (x0 in low half)
__device__ __forceinline__ void split2(float x0, float x1, unsigned& hi, unsigned& lo) {
    __nv_bfloat162 h = __floats2bfloat162_rn(x0, x1);
    hi = *reinterpret_cast<unsigned*>(&h);
    float2 hf = __bfloat1622float2(h);
    __nv_bfloat162 l = __floats2bfloat162_rn(x0 - hf.x, x1 - hf.y);
    lo = *reinterpret_cast<unsigned*>(&l);
}

// ---------------- octonion helpers (compile-time foldable) ------------------
__device__ __forceinline__ void qmul_d(const float* a, const float* b, float* r) {
    r[0] = a[0]*b[0] - a[1]*b[1] - a[2]*b[2] - a[3]*b[3];
    r[1] = a[0]*b[1] + a[1]*b[0] + a[2]*b[3] - a[3]*b[2];
    r[2] = a[0]*b[2] - a[1]*b[3] + a[2]*b[0] + a[3]*b[1];
    r[3] = a[0]*b[3] + a[1]*b[2] - a[2]*b[1] + a[3]*b[0];
}
__device__ __forceinline__ void omul_d(const float* x, const float* y, float* r) {
    float a[4] = {x[0], x[1], x[2], x[3]};
    float b[4] = {x[4], x[5], x[6], x[7]};
    float c[4] = {y[0], y[1], y[2], y[3]};
    float d[4] = {y[4], y[5], y[6], y[7]};
    float dc[4] = { d[0], -d[1], -d[2], -d[3] };
    float cc[4] = { c[0], -c[1], -c[2], -c[3] };
    float t1[4], t2[4], t3[4], t4[4];
    qmul_d(a,  c,  t1);
    qmul_d(dc, b,  t2);
    qmul_d(d,  a,  t3);
    qmul_d(b,  cc, t4);
    #pragma unroll
    for (int i = 0; i < 4; i++) { r[i]   = t1[i] - t2[i]; }
    #pragma unroll
    for (int i = 0; i < 4; i++) { r[4+i] = t3[i] + t4[i]; }
}

// ============================================================================
// bf16x3 MMA GEMM (NT): C[M,N] = alpha * A[M,K] @ B[N,K]^T
// BM=128, BN=64, BK=16, 256 threads (8 warps: 4m x 2n), warp tile 32x32.
// fp32 operands split into bf16 hi+lo; acc = hi*hi + hi*lo + lo*hi (fp32 acc).
// ============================================================================
__global__ __launch_bounds__(256) void mma_nt(
    const float* __restrict__ A, const float* __restrict__ B, float* __restrict__ C,
    int M, int N, int K, size_t sA, size_t sB, size_t sC, float alpha, int causal)
{
    const int m0 = blockIdx.y * 128;
    const int n0 = blockIdx.x * 64;
    if (causal && n0 > m0 + 127) return;
    A += (size_t)blockIdx.z * sA;
    B += (size_t)blockIdx.z * sB;
    C += (size_t)blockIdx.z * sC;

    __shared__ __align__(16) float As[2][128][20];  // [m][k], pad 4
    __shared__ __align__(16) float Bs[2][64][20];   // [n][k], pad 4

    const int tid  = threadIdx.x;
    const int warp = tid >> 5, lane = tid & 31;
    const int wm = (warp >> 1) * 32, wn = (warp & 1) * 32;
    const int g = lane >> 2, t = lane & 3;

    const int arow = tid >> 2;          // 0..63
    const int akc  = (tid & 3) * 4;     // 0,4,8,12

    float acc[2][4][4] = {};

    {
        CPA16(smem_u32(&As[0][arow][akc]),      &A[(size_t)(m0 + arow)      * K + akc]);
        CPA16(smem_u32(&As[0][arow + 64][akc]), &A[(size_t)(m0 + arow + 64) * K + akc]);
        CPA16(smem_u32(&Bs[0][arow][akc]),      &B[(size_t)(n0 + arow)      * K + akc]);
        CPCOMMIT();
    }

    int buf = 0;
    for (int k0 = 0; k0 < K; k0 += 16) {
        if (k0 + 16 < K) {
            const int kn = k0 + 16;
            CPA16(smem_u32(&As[buf ^ 1][arow][akc]),      &A[(size_t)(m0 + arow)      * K + kn + akc]);
            CPA16(smem_u32(&As[buf ^ 1][arow + 64][akc]), &A[(size_t)(m0 + arow + 64) * K + kn + akc]);
            CPA16(smem_u32(&Bs[buf ^ 1][arow][akc]),      &B[(size_t)(n0 + arow)      * K + kn + akc]);
            CPCOMMIT();
            CPWAIT1();
        } else {
            CPWAIT0();
        }
        __syncthreads();

        // fragment load + hi/lo split (one k16 step per tile)
        unsigned ah[2][4], al[2][4], bh[4][2], bl[4][2];
        #pragma unroll
        for (int mi = 0; mi < 2; mi++) {
            const int r = wm + mi * 16 + g;
            float2 p0 = *(const float2*)&As[buf][r][2 * t];
            float2 p1 = *(const float2*)&As[buf][r + 8][2 * t];
            float2 p2 = *(const float2*)&As[buf][r][2 * t + 8];
            float2 p3 = *(const float2*)&As[buf][r + 8][2 * t + 8];
            split2(p0.x, p0.y, ah[mi][0], al[mi][0]);
            split2(p1.x, p1.y, ah[mi][1], al[mi][1]);
            split2(p2.x, p2.y, ah[mi][2], al[mi][2]);
            split2(p3.x, p3.y, ah[mi][3], al[mi][3]);
        }
        #pragma unroll
        for (int ni = 0; ni < 4; ni++) {
            const int c = wn + ni * 8 + g;
            float2 p0 = *(const float2*)&Bs[buf][c][2 * t];
            float2 p1 = *(const float2*)&Bs[buf][c][2 * t + 8];
            split2(p0.x, p0.y, bh[ni][0], bl[ni][0]);
            split2(p1.x, p1.y, bh[ni][1], bl[ni][1]);
        }
        #pragma unroll
        for (int mi = 0; mi < 2; mi++)
            #pragma unroll
            for (int ni = 0; ni < 4; ni++) {
                mma16(acc[mi][ni], ah[mi], bh[ni]);
                mma16(acc[mi][ni], ah[mi], bl[ni]);
                mma16(acc[mi][ni], al[mi], bh[ni]);
            }
        __syncthreads();
        buf ^= 1;
    }

    #pragma unroll
    for (int mi = 0; mi < 2; mi++)
        #pragma unroll
        for (int ni = 0; ni < 4; ni++) {
            const int row = m0 + wm + mi * 16 + g;
            const int col = n0 + wn + ni * 8 + 2 * t;
            float2 v0 = make_float2(alpha * acc[mi][ni][0], alpha * acc[mi][ni][1]);
            float2 v1 = make_float2(alpha * acc[mi][ni][2], alpha * acc[mi][ni][3]);
            *(float2*)&C[(size_t)row * N + col]       = v0;
            *(float2*)&C[(size_t)(row + 8) * N + col] = v1;
        }
}

// ============================================================================
// bf16x3 MMA GEMM (NN, causal-masked A): z[h] = att[h](j<=i) @ kv[h]
// ============================================================================
__global__ __launch_bounds__(256) void mma_z(
    const float* __restrict__ att, const float* __restrict__ kvm, float* __restrict__ z)
{
    const int h  = blockIdx.z;
    const int m0 = blockIdx.y * 128;
    const int n0 = blockIdx.x * 64;
    const float* A = att + (size_t)h * T_SEQ * T_SEQ;
    const float* B = kvm + (size_t)h * T_SEQ * KVW;
    float* C = z + (size_t)h * T_SEQ * KVW;
    const int Kend = m0 + 128;

    __shared__ __align__(16) float As[2][128][20];  // [m][k], pad 4
    __shared__ __align__(16) float Bs[2][16][72];   // [k][n], pad 8

    const int tid  = threadIdx.x;
    const int warp = tid >> 5, lane = tid & 31;
    const int wm = (warp >> 1) * 32, wn = (warp & 1) * 32;
    const int g = lane >> 2, t = lane & 3;

    const int arow = tid >> 2;          // 0..63
    const int akc  = (tid & 3) * 4;
    const int bkr  = tid >> 4;          // 0..15
    const int bnc  = (tid & 15) * 4;    // 0..60

    float acc[2][4][4] = {};

    {
        CPA16(smem_u32(&As[0][arow][akc]),      &A[(size_t)(m0 + arow)      * T_SEQ + akc]);
        CPA16(smem_u32(&As[0][arow + 64][akc]), &A[(size_t)(m0 + arow + 64) * T_SEQ + akc]);
        CPA16(smem_u32(&Bs[0][bkr][bnc]),       &B[(size_t)bkr * KVW + n0 + bnc]);
        CPCOMMIT();
    }

    int buf = 0;
    for (int k0 = 0; k0 < Kend; k0 += 16) {
        if (k0 + 16 < Kend) {
            const int kn = k0 + 16;
            CPA16(smem_u32(&As[buf ^ 1][arow][akc]),      &A[(size_t)(m0 + arow)      * T_SEQ + kn + akc]);
            CPA16(smem_u32(&As[buf ^ 1][arow + 64][akc]), &A[(size_t)(m0 + arow + 64) * T_SEQ + kn + akc]);
            CPA16(smem_u32(&Bs[buf ^ 1][bkr][bnc]),       &B[(size_t)(kn + bkr) * KVW + n0 + bnc]);
            CPCOMMIT();
            CPWAIT1();
        } else {
            CPWAIT0();
        }
        __syncthreads();

        if (k0 >= m0) {  // diagonal region: zero above-diagonal A entries
            #pragma unroll
            for (int half = 0; half < 2; half++) {
                const int row = arow + half * 64;
                const int ig  = m0 + row;
                #pragma unroll
                for (int c = 0; c < 4; c++)
                    if (k0 + akc + c > ig) As[buf][row][akc + c] = 0.0f;
            }
            __syncthreads();
        }

        unsigned ah[2][4], al[2][4], bh[4][2], bl[4][2];
        #pragma unroll
        for (int mi = 0; mi < 2; mi++) {
            const int r = wm + mi * 16 + g;
            float2 p0 = *(const float2*)&As[buf][r][2 * t];
            float2 p1 = *(const float2*)&As[buf][r + 8][2 * t];
            float2 p2 = *(const float2*)&As[buf][r][2 * t + 8];
            float2 p3 = *(const float2*)&As[buf][r + 8][2 * t + 8];
            split2(p0.x, p0.y, ah[mi][0], al[mi][0]);
            split2(p1.x, p1.y, ah[mi][1], al[mi][1]);
            split2(p2.x, p2.y, ah[mi][2], al[mi][2]);
            split2(p3.x, p3.y, ah[mi][3], al[mi][3]);
        }
        #pragma unroll
        for (int ni = 0; ni < 4; ni++) {
            const int c = wn + ni * 8 + g;
            split2(Bs[buf][2 * t][c],     Bs[buf][2 * t + 1][c], bh[ni][0], bl[ni][0]);
            split2(Bs[buf][2 * t + 8][c], Bs[buf][2 * t + 9][c], bh[ni][1], bl[ni][1]);
        }
        #pragma unroll
        for (int mi = 0; mi < 2; mi++)
            #pragma unroll
            for (int ni = 0; ni < 4; ni++) {
                mma16(acc[mi][ni], ah[mi], bh[ni]);
                mma16(acc[mi][ni], ah[mi], bl[ni]);
                mma16(acc[mi][ni], al[mi], bh[ni]);
            }
        __syncthreads();
        buf ^= 1;
    }

    #pragma unroll
    for (int mi = 0; mi < 2; mi++)
        #pragma unroll
        for (int ni = 0; ni < 4; ni++) {
            const int row = m0 + wm + mi * 16 + g;
            const int col = n0 + wn + ni * 8 + 2 * t;
            float2 v0 = make_float2(acc[mi][ni][0], acc[mi][ni][1]);
            float2 v1 = make_float2(acc[mi][ni][2], acc[mi][ni][3]);
            *(float2*)&C[(size_t)row * KVW + col]       = v0;
            *(float2*)&C[(size_t)(row + 8) * KVW + col] = v1;
        }
}

// ---------------- fused RoPE + RMS + octonion conj-unit + KV outer ----------
__global__ __launch_bounds__(512) void rope_rms_kv(
    const float* __restrict__ qraw, const float* __restrict__ kraw,
    const float* __restrict__ vraw, const float* __restrict__ cosb,
    const float* __restrict__ sinb,
    float* __restrict__ qh, float* __restrict__ kh, float* __restrict__ kv)
{
    const int t = blockIdx.x;
    const int h = threadIdx.x >> 5;
    const int lane = threadIdx.x & 31;
    const unsigned FULL = 0xffffffffu;

    const float c = cosb[t * 32 + lane];
    const float s = sinb[t * 32 + lane];
    const size_t base = (size_t)t * NE + (size_t)h * HD;
    float q1 = qraw[base + lane], q2 = qraw[base + lane + 32];
    float k1 = kraw[base + lane], k2 = kraw[base + lane + 32];
    float v1 = vraw[base + lane], v2 = vraw[base + lane + 32];

    float qr1 = q1 * c + q2 * s, qr2 = q2 * c - q1 * s;
    float kr1 = k1 * c + k2 * s, kr2 = k2 * c - k1 * s;

    float sq = qr1 * qr1 + qr2 * qr2;
    float sk = kr1 * kr1 + kr2 * kr2;
    #pragma unroll
    for (int off = 16; off > 0; off >>= 1) {
        sq += __shfl_xor_sync(FULL, sq, off);
        sk += __shfl_xor_sync(FULL, sk, off);
    }
    const float rq = rsqrtf(sq * (1.0f / 64.0f) + 1e-6f);
    const float rk = rsqrtf(sk * (1.0f / 64.0f) + 1e-6f);
    qr1 *= rq; qr2 *= rq;
    kr1 *= rk; kr2 *= rk;

    const size_t hb = ((size_t)h * T_SEQ + t) * HD;
    qh[hb + lane] = qr1; qh[hb + lane + 32] = qr2;
    kh[hb + lane] = kr1; kh[hb + lane + 32] = kr2;

    float g1 = kr1 * kr1, g2 = kr2 * kr2;
    #pragma unroll
    for (int off = 1; off < 8; off <<= 1) {
        g1 += __shfl_xor_sync(FULL, g1, off);
        g2 += __shfl_xor_sync(FULL, g2, off);
    }
    const float sgn = ((lane & 7) == 0) ? 1.0f : -1.0f;
    const float kc1 = sgn * kr1 / fmaxf(sqrtf(g1), 1e-12f);
    const float kc2 = sgn * kr2 / fmaxf(sqrtf(g2), 1e-12f);

    __shared__ float skc[16][64];
    __shared__ float sv[16][64];
    skc[h][lane] = kc1; skc[h][lane + 32] = kc2;
    sv[h][lane]  = v1;  sv[h][lane + 32]  = v2;
    __syncwarp();

    float* kvrow = kv + ((size_t)h * T_SEQ + t) * KVW;
    #pragma unroll
    for (int r = 0; r < 16; r++) {
        int n = lane + 32 * r;
        int m = n >> 6, p = (n >> 3) & 7, q = n & 7;
        kvrow[n] = skc[h][m * 8 + p] * sv[h][m * 8 + q];
    }
}

// ---------------- softmax rows (in-place, causal length i+1) ----------------
__global__ __launch_bounds__(256) void softmax_rows(float* __restrict__ att)
{
    const int i = blockIdx.x;
    const int h = blockIdx.y;
    float* row = att + (size_t)h * T_SEQ * T_SEQ + (size_t)i * T_SEQ;
    const int n = i + 1;
    const int tid = threadIdx.x;

    float v[8];
    int cnt = 0;
    float mx = -1e30f;
    for (int j = tid; j < n; j += 256) {
        float x = row[j];
        v[cnt++] = x;
        mx = fmaxf(mx, x);
    }
    __shared__ float red[256];
    red[tid] = mx; __syncthreads();
    #pragma unroll
    for (int s = 128; s > 0; s >>= 1) {
        if (tid < s) red[tid] = fmaxf(red[tid], red[tid + s]);
        __syncthreads();
    }
    mx = red[0]; __syncthreads();

    float sum = 0.0f;
    for (int c2 = 0; c2 < cnt; c2++) { v[c2] = __expf(v[c2] - mx); sum += v[c2]; }
    red[tid] = sum; __syncthreads();
    #pragma unroll
    for (int s = 128; s > 0; s >>= 1) {
        if (tid < s) red[tid] += red[tid + s];
        __syncthreads();
    }
    const float inv = 1.0f / red[0];
    cnt = 0;
    for (int j = tid; j < n; j += 256) row[j] = v[cnt++] * inv;
}

// ---------------- final octonion contraction: y = sum_p (u o e_p) o Z_p -----
__global__ __launch_bounds__(256) void y_contract(
    const float* __restrict__ qh, const float* __restrict__ z,
    float* __restrict__ ypre)
{
    const int gid = blockIdx.x * blockDim.x + threadIdx.x;
    const int t = gid >> 7;
    const int r = gid & 127;
    const int h = r >> 3;
    const int m = r & 7;

    const float* u_ptr = qh + ((size_t)h * T_SEQ + t) * HD + m * 8;
    const float* zr = z + ((size_t)h * T_SEQ + t) * KVW + m * 64;

    float u[8];
    #pragma unroll
    for (int i = 0; i < 8; i++) u[i] = u_ptr[i];

    float y[8] = {};
    #pragma unroll
    for (int p = 0; p < 8; p++) {
        float ep[8] = {};
        ep[p] = 1.0f;
        float w[8];
        omul_d(u, ep, w);
        float zp[8];
        #pragma unroll
        for (int q = 0; q < 8; q++) zp[q] = zr[p * 8 + q];
        float tt[8];
        omul_d(w, zp, tt);
        #pragma unroll
        for (int k = 0; k < 8; k++) y[k] += tt[k];
    }
    float* out = ypre + (size_t)t * NE + h * 64 + m * 8;
    #pragma unroll
    for (int k = 0; k < 8; k++) out[k] = y[k];
}

// ---------------- launch ----------------------------------------------------
extern "C" void kernel_launch(void* const* d_in, const int* in_sizes, int n_in,
                              void* d_out, int out_size)
{
    const float* x    = (const float*)d_in[0];
    const float* cosb = (const float*)d_in[1];
    const float* sinb = (const float*)d_in[2];
    const float* Wq   = (const float*)d_in[3];
    const float* Wk   = (const float*)d_in[4];
    const float* Wv   = (const float*)d_in[5];
    const float* Wo   = (const float*)d_in[6];
    float* out = (float*)d_out;

    float *qraw, *kraw, *vraw, *qh, *kh, *kv, *att, *z, *ypre;
    cudaGetSymbolAddress((void**)&qraw, g_qraw);
    cudaGetSymbolAddress((void**)&kraw, g_kraw);
    cudaGetSymbolAddress((void**)&vraw, g_vraw);
    cudaGetSymbolAddress((void**)&qh,   g_qh);
    cudaGetSymbolAddress((void**)&kh,   g_kh);
    cudaGetSymbolAddress((void**)&kv,   g_kv);
    cudaGetSymbolAddress((void**)&att,  g_att);
    cudaGetSymbolAddress((void**)&z,    g_z);
    cudaGetSymbolAddress((void**)&ypre, g_ypre);

    const size_t sQK  = (size_t)T_SEQ * HD;
    const size_t sAtt = (size_t)T_SEQ * T_SEQ;

    // 1-3: QKV projections  C[2048,1024] = x @ W^T
    dim3 gproj(NE / 64, T_SEQ / 128, 1);
    mma_nt<<<gproj, 256>>>(x, Wq, qraw, T_SEQ, NE, NE, 0, 0, 0, 1.0f, 0);
    mma_nt<<<gproj, 256>>>(x, Wk, kraw, T_SEQ, NE, NE, 0, 0, 0, 1.0f, 0);
    mma_nt<<<gproj, 256>>>(x, Wv, vraw, T_SEQ, NE, NE, 0, 0, 0, 1.0f, 0);

    // 4: rope + rms + octonion conj/unit + KV outer products
    rope_rms_kv<<<T_SEQ, 512>>>(qraw, kraw, vraw, cosb, sinb, qh, kh, kv);

    // 5: scores = (qh @ kh^T) / 8 per head, causal block-skip
    dim3 gsc(T_SEQ / 64, T_SEQ / 128, NH);
    mma_nt<<<gsc, 256>>>(qh, kh, att, T_SEQ, T_SEQ, HD, sQK, sQK, sAtt, 0.125f, 1);

    // 6: softmax
    softmax_rows<<<dim3(T_SEQ, NH), 256>>>(att);

    // 7: Z = probs @ KV (causal)
    dim3 gz(KVW / 64, T_SEQ / 128, NH);
    mma_z<<<gz, 256>>>(att, kv, z);

    // 8: octonion contraction -> ypre [T, NE]
    y_contract<<<(T_SEQ * NH * 8) / 256, 256>>>(qh, z, ypre);

    // 9: output projection
    dim3 gout(NE / 64, T_SEQ / 128, 1);
    mma_nt<<<gout, 256>>>(ypre, Wo, out, T_SEQ, NE, NE, 0, 0, 0, 1.0f, 0);
}

// round 8
// speedup vs baseline: 1.6870x; 1.2608x over previous
#include <cuda_runtime.h>
#include <cuda_bf16.h>
#include <math.h>

#define T_SEQ 2048
#define NH 16
#define HD 64
#define NE 1024
#define KVW 512

typedef __nv_bfloat16 bf16;

// ---------------- scratch (static device globals) ---------------------------
__device__ float g_qraw[(size_t)T_SEQ * NE];
__device__ float g_kraw[(size_t)T_SEQ * NE];
__device__ float g_vraw[(size_t)T_SEQ * NE];
__device__ float g_qh[(size_t)NH * T_SEQ * HD];      // fp32 for y_contract
__device__ float g_att[(size_t)NH * T_SEQ * T_SEQ];  // fp32 scores
__device__ float g_z[(size_t)NH * T_SEQ * KVW];
__device__ float g_out_dummy[1];

// bf16 hi/lo planes
__device__ bf16 g_xh[(size_t)T_SEQ * NE],  g_xl[(size_t)T_SEQ * NE];
__device__ bf16 g_wqh[(size_t)NE * NE],    g_wql[(size_t)NE * NE];
__device__ bf16 g_wkh[(size_t)NE * NE],    g_wkl[(size_t)NE * NE];
__device__ bf16 g_wvh[(size_t)NE * NE],    g_wvl[(size_t)NE * NE];
__device__ bf16 g_woh[(size_t)NE * NE],    g_wol[(size_t)NE * NE];
__device__ bf16 g_qhh[(size_t)NH * T_SEQ * HD],  g_qhl[(size_t)NH * T_SEQ * HD];
__device__ bf16 g_khh[(size_t)NH * T_SEQ * HD],  g_khl[(size_t)NH * T_SEQ * HD];
__device__ bf16 g_kvh[(size_t)NH * T_SEQ * KVW], g_kvl[(size_t)NH * T_SEQ * KVW];
__device__ bf16 g_atth[(size_t)NH * T_SEQ * T_SEQ], g_attl[(size_t)NH * T_SEQ * T_SEQ];
__device__ bf16 g_yph[(size_t)T_SEQ * NE], g_ypl[(size_t)T_SEQ * NE];

// ---------------- helpers ----------------------------------------------------
__device__ __forceinline__ unsigned smem_u32(const void* p) {
    return (unsigned)__cvta_generic_to_shared(p);
}
#define CPA16(dst_u32, src_ptr) \
    asm volatile("cp.async.cg.shared.global [%0], [%1], 16;" :: "r"(dst_u32), "l"(src_ptr))
#define CPCOMMIT() asm volatile("cp.async.commit_group;")
#define CPWAIT1()  asm volatile("cp.async.wait_group 1;")
#define CPWAIT0()  asm volatile("cp.async.wait_group 0;")

__device__ __forceinline__ void mma16(float* d, const unsigned* a, const unsigned* b) {
    asm volatile(
        "mma.sync.aligned.m16n8k16.row.col.f32.bf16.bf16.f32 "
        "{%0,%1,%2,%3},{%4,%5,%6,%7},{%8,%9},{%0,%1,%2,%3};"
        : "+f"(d[0]), "+f"(d[1]), "+f"(d[2]), "+f"(d[3])
        : "r"(a[0]), "r"(a[1]), "r"(a[2]), "r"(a[3]), "r"(b[0]), "r"(b[1]));
}
__device__ __forceinline__ void ldsm4(unsigned* r, unsigned a) {
    asm volatile("ldmatrix.sync.aligned.m8n8.x4.shared.b16 {%0,%1,%2,%3}, [%4];"
        : "=r"(r[0]), "=r"(r[1]), "=r"(r[2]), "=r"(r[3]) : "r"(a));
}
__device__ __forceinline__ void ldsm4t(unsigned* r, unsigned a) {
    asm volatile("ldmatrix.sync.aligned.m8n8.x4.trans.shared.b16 {%0,%1,%2,%3}, [%4];"
        : "=r"(r[0]), "=r"(r[1]), "=r"(r[2]), "=r"(r[3]) : "r"(a));
}
__device__ __forceinline__ void split2(float x0, float x1, unsigned& hi, unsigned& lo) {
    __nv_bfloat162 h = __floats2bfloat162_rn(x0, x1);
    hi = *reinterpret_cast<unsigned*>(&h);
    float2 hf = __bfloat1622float2(h);
    __nv_bfloat162 l = __floats2bfloat162_rn(x0 - hf.x, x1 - hf.y);
    lo = *reinterpret_cast<unsigned*>(&l);
}
__device__ __forceinline__ void split1(float x, bf16& hi, bf16& lo) {
    hi = __float2bfloat16(x);
    lo = __float2bfloat16(x - __bfloat162float(hi));
}

// ---------------- split kernel ----------------------------------------------
__global__ __launch_bounds__(256) void split_f32(
    const float* __restrict__ s, bf16* __restrict__ h, bf16* __restrict__ l, int n)
{
    int i = (blockIdx.x * 256 + threadIdx.x) * 2;
    if (i < n) {
        float2 v = *(const float2*)&s[i];
        unsigned hh, ll;
        split2(v.x, v.y, hh, ll);
        *(unsigned*)&h[i] = hh;
        *(unsigned*)&l[i] = ll;
    }
}

// ---------------- octonion helpers ------------------------------------------
__device__ __forceinline__ void qmul_d(const float* a, const float* b, float* r) {
    r[0] = a[0]*b[0] - a[1]*b[1] - a[2]*b[2] - a[3]*b[3];
    r[1] = a[0]*b[1] + a[1]*b[0] + a[2]*b[3] - a[3]*b[2];
    r[2] = a[0]*b[2] - a[1]*b[3] + a[2]*b[0] + a[3]*b[1];
    r[3] = a[0]*b[3] + a[1]*b[2] - a[2]*b[1] + a[3]*b[0];
}
__device__ __forceinline__ void omul_d(const float* x, const float* y, float* r) {
    float a[4] = {x[0], x[1], x[2], x[3]};
    float b[4] = {x[4], x[5], x[6], x[7]};
    float c[4] = {y[0], y[1], y[2], y[3]};
    float d[4] = {y[4], y[5], y[6], y[7]};
    float dc[4] = { d[0], -d[1], -d[2], -d[3] };
    float cc[4] = { c[0], -c[1], -c[2], -c[3] };
    float t1[4], t2[4], t3[4], t4[4];
    qmul_d(a,  c,  t1);
    qmul_d(dc, b,  t2);
    qmul_d(d,  a,  t3);
    qmul_d(b,  cc, t4);
    #pragma unroll
    for (int i = 0; i < 4; i++) { r[i]   = t1[i] - t2[i]; }
    #pragma unroll
    for (int i = 0; i < 4; i++) { r[4+i] = t3[i] + t4[i]; }
}

// ============================================================================
// bf16-plane MMA GEMM (NT): C[M,N] = alpha * (Ah+Al)[M,K] @ (Bh+Bl)[N,K]^T
// BM=128, BN=64, BK=32, 256 threads (8 warps 4m x 2n), warp tile 32x32.
// Inner loop: LDSM.x4 fragment loads + 3-term compensated bf16 MMA.
// ============================================================================
__global__ __launch_bounds__(256) void bf_nt(
    const bf16* __restrict__ Ah, const bf16* __restrict__ Al,
    const bf16* __restrict__ Bh, const bf16* __restrict__ Bl,
    float* __restrict__ C,
    int M, int N, int K, size_t sA, size_t sB, size_t sC, float alpha, int causal)
{
    const int m0 = blockIdx.y * 128;
    const int n0 = blockIdx.x * 64;
    if (causal && n0 > m0 + 127) return;
    Ah += (size_t)blockIdx.z * sA;  Al += (size_t)blockIdx.z * sA;
    Bh += (size_t)blockIdx.z * sB;  Bl += (size_t)blockIdx.z * sB;
    C  += (size_t)blockIdx.z * sC;

    __shared__ __align__(16) bf16 As[2][2][128][40];  // [buf][plane][m][k] pad8
    __shared__ __align__(16) bf16 Bs[2][2][64][40];   // [buf][plane][n][k] pad8

    const int tid  = threadIdx.x;
    const int warp = tid >> 5, lane = tid & 31;
    const int wm = (warp >> 1) * 32, wn = (warp & 1) * 32;

    const int arow = tid >> 2;        // 0..63
    const int akc  = (tid & 3) * 8;   // k chunk (8 bf16 = 16B)

    float acc[2][4][4] = {};

    const bf16* Ap[2] = {Ah, Al};
    const bf16* Bp[2] = {Bh, Bl};

    // prefetch tile 0
    #pragma unroll
    for (int p = 0; p < 2; p++) {
        CPA16(smem_u32(&As[0][p][arow][akc]),      &Ap[p][(size_t)(m0 + arow)      * K + akc]);
        CPA16(smem_u32(&As[0][p][arow + 64][akc]), &Ap[p][(size_t)(m0 + arow + 64) * K + akc]);
        CPA16(smem_u32(&Bs[0][p][arow][akc]),      &Bp[p][(size_t)(n0 + arow)      * K + akc]);
    }
    CPCOMMIT();

    int buf = 0;
    for (int k0 = 0; k0 < K; k0 += 32) {
        if (k0 + 32 < K) {
            const int kn = k0 + 32;
            #pragma unroll
            for (int p = 0; p < 2; p++) {
                CPA16(smem_u32(&As[buf ^ 1][p][arow][akc]),      &Ap[p][(size_t)(m0 + arow)      * K + kn + akc]);
                CPA16(smem_u32(&As[buf ^ 1][p][arow + 64][akc]), &Ap[p][(size_t)(m0 + arow + 64) * K + kn + akc]);
                CPA16(smem_u32(&Bs[buf ^ 1][p][arow][akc]),      &Bp[p][(size_t)(n0 + arow)      * K + kn + akc]);
            }
            CPCOMMIT();
            CPWAIT1();
        } else {
            CPWAIT0();
        }
        __syncthreads();

        #pragma unroll
        for (int kk = 0; kk < 32; kk += 16) {
            unsigned a_h[2][4], a_l[2][4], b_h[8], b_l[8];
            #pragma unroll
            for (int mi = 0; mi < 2; mi++) {
                ldsm4(a_h[mi], smem_u32(&As[buf][0][wm + mi*16 + (lane & 15)][kk + ((lane >> 4) << 3)]));
                ldsm4(a_l[mi], smem_u32(&As[buf][1][wm + mi*16 + (lane & 15)][kk + ((lane >> 4) << 3)]));
            }
            {
                const int br = wn + (lane & 7) + ((lane >> 4) << 3);
                const int bc = kk + (((lane >> 3) & 1) << 3);
                ldsm4(&b_h[0], smem_u32(&Bs[buf][0][br][bc]));
                ldsm4(&b_l[0], smem_u32(&Bs[buf][1][br][bc]));
                ldsm4(&b_h[4], smem_u32(&Bs[buf][0][br + 16][bc]));
                ldsm4(&b_l[4], smem_u32(&Bs[buf][1][br + 16][bc]));
            }
            #pragma unroll
            for (int mi = 0; mi < 2; mi++)
                #pragma unroll
                for (int ni = 0; ni < 4; ni++) {
                    mma16(acc[mi][ni], a_h[mi], &b_h[ni*2]);
                    mma16(acc[mi][ni], a_h[mi], &b_l[ni*2]);
                    mma16(acc[mi][ni], a_l[mi], &b_h[ni*2]);
                }
        }
        __syncthreads();
        buf ^= 1;
    }

    const int g = lane >> 2, t = lane & 3;
    #pragma unroll
    for (int mi = 0; mi < 2; mi++)
        #pragma unroll
        for (int ni = 0; ni < 4; ni++) {
            const int row = m0 + wm + mi * 16 + g;
            const int col = n0 + wn + ni * 8 + 2 * t;
            float2 v0 = make_float2(alpha * acc[mi][ni][0], alpha * acc[mi][ni][1]);
            float2 v1 = make_float2(alpha * acc[mi][ni][2], alpha * acc[mi][ni][3]);
            *(float2*)&C[(size_t)row * N + col]       = v0;
            *(float2*)&C[(size_t)(row + 8) * N + col] = v1;
        }
}

// ============================================================================
// z-GEMM (NN, causal): z[h] = att[h](j<=i) @ kv[h]; bf16 planes, trans LDSM B.
// ============================================================================
__global__ __launch_bounds__(256) void bf_z(
    const bf16* __restrict__ Ahh, const bf16* __restrict__ All,
    const bf16* __restrict__ Bhh, const bf16* __restrict__ Bll,
    float* __restrict__ z)
{
    const int h  = blockIdx.z;
    const int m0 = blockIdx.y * 128;
    const int n0 = blockIdx.x * 64;
    const bf16* Ap[2] = { Ahh + (size_t)h * T_SEQ * T_SEQ, All + (size_t)h * T_SEQ * T_SEQ };
    const bf16* Bp[2] = { Bhh + (size_t)h * T_SEQ * KVW,  Bll + (size_t)h * T_SEQ * KVW };
    float* C = z + (size_t)h * T_SEQ * KVW;
    const int Kend = m0 + 128;

    __shared__ __align__(16) bf16 As[2][2][128][40];  // [buf][plane][m][k] pad8
    __shared__ __align__(16) bf16 Bs[2][2][32][72];   // [buf][plane][k][n] pad8

    const int tid  = threadIdx.x;
    const int warp = tid >> 5, lane = tid & 31;
    const int wm = (warp >> 1) * 32, wn = (warp & 1) * 32;

    const int arow = tid >> 2;        // 0..63
    const int akc  = (tid & 3) * 8;
    const int bkr  = tid >> 3;        // 0..31
    const int bnc  = (tid & 7) * 8;   // 0..56

    float acc[2][4][4] = {};

    #pragma unroll
    for (int p = 0; p < 2; p++) {
        CPA16(smem_u32(&As[0][p][arow][akc]),      &Ap[p][(size_t)(m0 + arow)      * T_SEQ + akc]);
        CPA16(smem_u32(&As[0][p][arow + 64][akc]), &Ap[p][(size_t)(m0 + arow + 64) * T_SEQ + akc]);
        CPA16(smem_u32(&Bs[0][p][bkr][bnc]),       &Bp[p][(size_t)bkr * KVW + n0 + bnc]);
    }
    CPCOMMIT();

    const bf16 z0 = __float2bfloat16(0.0f);

    int buf = 0;
    for (int k0 = 0; k0 < Kend; k0 += 32) {
        if (k0 + 32 < Kend) {
            const int kn = k0 + 32;
            #pragma unroll
            for (int p = 0; p < 2; p++) {
                CPA16(smem_u32(&As[buf ^ 1][p][arow][akc]),      &Ap[p][(size_t)(m0 + arow)      * T_SEQ + kn + akc]);
                CPA16(smem_u32(&As[buf ^ 1][p][arow + 64][akc]), &Ap[p][(size_t)(m0 + arow + 64) * T_SEQ + kn + akc]);
                CPA16(smem_u32(&Bs[buf ^ 1][p][bkr][bnc]),       &Bp[p][(size_t)(kn + bkr) * KVW + n0 + bnc]);
            }
            CPCOMMIT();
            CPWAIT1();
        } else {
            CPWAIT0();
        }
        __syncthreads();

        if (k0 >= m0) {  // diagonal band: zero above-diagonal A entries
            const int row = tid >> 1;            // 0..127
            const int i   = m0 + row;
            const int cb  = (tid & 1) * 16;
            #pragma unroll
            for (int c = 0; c < 16; c++) {
                if (k0 + cb + c > i) {
                    As[buf][0][row][cb + c] = z0;
                    As[buf][1][row][cb + c] = z0;
                }
            }
            __syncthreads();
        }

        #pragma unroll
        for (int kk = 0; kk < 32; kk += 16) {
            unsigned a_h[2][4], a_l[2][4], b_h[8], b_l[8];
            #pragma unroll
            for (int mi = 0; mi < 2; mi++) {
                ldsm4(a_h[mi], smem_u32(&As[buf][0][wm + mi*16 + (lane & 15)][kk + ((lane >> 4) << 3)]));
                ldsm4(a_l[mi], smem_u32(&As[buf][1][wm + mi*16 + (lane & 15)][kk + ((lane >> 4) << 3)]));
            }
            {
                const int kr = kk + (lane & 7) + (((lane >> 3) & 1) << 3);
                const int nc = wn + ((lane >> 4) << 3);
                ldsm4t(&b_h[0], smem_u32(&Bs[buf][0][kr][nc]));
                ldsm4t(&b_l[0], smem_u32(&Bs[buf][1][kr][nc]));
                ldsm4t(&b_h[4], smem_u32(&Bs[buf][0][kr][nc + 16]));
                ldsm4t(&b_l[4], smem_u32(&Bs[buf][1][kr][nc + 16]));
            }
            #pragma unroll
            for (int mi = 0; mi < 2; mi++)
                #pragma unroll
                for (int ni = 0; ni < 4; ni++) {
                    mma16(acc[mi][ni], a_h[mi], &b_h[ni*2]);
                    mma16(acc[mi][ni], a_h[mi], &b_l[ni*2]);
                    mma16(acc[mi][ni], a_l[mi], &b_h[ni*2]);
                }
        }
        __syncthreads();
        buf ^= 1;
    }

    const int g = lane >> 2, t = lane & 3;
    #pragma unroll
    for (int mi = 0; mi < 2; mi++)
        #pragma unroll
        for (int ni = 0; ni < 4; ni++) {
            const int row = m0 + wm + mi * 16 + g;
            const int col = n0 + wn + ni * 8 + 2 * t;
            float2 v0 = make_float2(acc[mi][ni][0], acc[mi][ni][1]);
            float2 v1 = make_float2(acc[mi][ni][2], acc[mi][ni][3]);
            *(float2*)&C[(size_t)row * KVW + col]       = v0;
            *(float2*)&C[(size_t)(row + 8) * KVW + col] = v1;
        }
}

// ---------------- fused RoPE + RMS + octonion conj-unit + KV outer ----------
__global__ __launch_bounds__(512) void rope_rms_kv(
    const float* __restrict__ qraw, const float* __restrict__ kraw,
    const float* __restrict__ vraw, const float* __restrict__ cosb,
    const float* __restrict__ sinb,
    float* __restrict__ qh,
    bf16* __restrict__ qhh, bf16* __restrict__ qhl,
    bf16* __restrict__ khh, bf16* __restrict__ khl,
    bf16* __restrict__ kvh, bf16* __restrict__ kvl)
{
    const int t = blockIdx.x;
    const int h = threadIdx.x >> 5;
    const int lane = threadIdx.x & 31;
    const unsigned FULL = 0xffffffffu;

    const float c = cosb[t * 32 + lane];
    const float s = sinb[t * 32 + lane];
    const size_t base = (size_t)t * NE + (size_t)h * HD;
    float q1 = qraw[base + lane], q2 = qraw[base + lane + 32];
    float k1 = kraw[base + lane], k2 = kraw[base + lane + 32];
    float v1 = vraw[base + lane], v2 = vraw[base + lane + 32];

    float qr1 = q1 * c + q2 * s, qr2 = q2 * c - q1 * s;
    float kr1 = k1 * c + k2 * s, kr2 = k2 * c - k1 * s;

    float sq = qr1 * qr1 + qr2 * qr2;
    float sk = kr1 * kr1 + kr2 * kr2;
    #pragma unroll
    for (int off = 16; off > 0; off >>= 1) {
        sq += __shfl_xor_sync(FULL, sq, off);
        sk += __shfl_xor_sync(FULL, sk, off);
    }
    const float rq = rsqrtf(sq * (1.0f / 64.0f) + 1e-6f);
    const float rk = rsqrtf(sk * (1.0f / 64.0f) + 1e-6f);
    qr1 *= rq; qr2 *= rq;
    kr1 *= rk; kr2 *= rk;

    const size_t hb = ((size_t)h * T_SEQ + t) * HD;
    qh[hb + lane] = qr1; qh[hb + lane + 32] = qr2;
    {
        bf16 hi, lo;
        split1(qr1, hi, lo); qhh[hb + lane] = hi;      qhl[hb + lane] = lo;
        split1(qr2, hi, lo); qhh[hb + lane + 32] = hi; qhl[hb + lane + 32] = lo;
        split1(kr1, hi, lo); khh[hb + lane] = hi;      khl[hb + lane] = lo;
        split1(kr2, hi, lo); khh[hb + lane + 32] = hi; khl[hb + lane + 32] = lo;
    }

    float g1 = kr1 * kr1, g2 = kr2 * kr2;
    #pragma unroll
    for (int off = 1; off < 8; off <<= 1) {
        g1 += __shfl_xor_sync(FULL, g1, off);
        g2 += __shfl_xor_sync(FULL, g2, off);
    }
    const float sgn = ((lane & 7) == 0) ? 1.0f : -1.0f;
    const float kc1 = sgn * kr1 / fmaxf(sqrtf(g1), 1e-12f);
    const float kc2 = sgn * kr2 / fmaxf(sqrtf(g2), 1e-12f);

    __shared__ float skc[16][64];
    __shared__ float sv[16][64];
    skc[h][lane] = kc1; skc[h][lane + 32] = kc2;
    sv[h][lane]  = v1;  sv[h][lane + 32]  = v2;
    __syncwarp();

    const size_t kvb = ((size_t)h * T_SEQ + t) * KVW;
    #pragma unroll
    for (int r = 0; r < 16; r++) {
        int n = lane + 32 * r;
        int m = n >> 6, p = (n >> 3) & 7, q = n & 7;
        float val = skc[h][m * 8 + p] * sv[h][m * 8 + q];
        bf16 hi, lo;
        split1(val, hi, lo);
        kvh[kvb + n] = hi;
        kvl[kvb + n] = lo;
    }
}

// ---------------- softmax rows (causal length i+1) -> bf16 hi/lo planes -----
__global__ __launch_bounds__(256) void softmax_rows(
    const float* __restrict__ att, bf16* __restrict__ atth, bf16* __restrict__ attl)
{
    const int i = blockIdx.x;
    const int h = blockIdx.y;
    const float* row = att + (size_t)h * T_SEQ * T_SEQ + (size_t)i * T_SEQ;
    bf16* rh = atth + (size_t)h * T_SEQ * T_SEQ + (size_t)i * T_SEQ;
    bf16* rl = attl + (size_t)h * T_SEQ * T_SEQ + (size_t)i * T_SEQ;
    const int n = i + 1;
    const int tid = threadIdx.x;

    float v[8];
    int cnt = 0;
    float mx = -1e30f;
    for (int j = tid; j < n; j += 256) {
        float x = row[j];
        v[cnt++] = x;
        mx = fmaxf(mx, x);
    }
    __shared__ float red[256];
    red[tid] = mx; __syncthreads();
    #pragma unroll
    for (int s = 128; s > 0; s >>= 1) {
        if (tid < s) red[tid] = fmaxf(red[tid], red[tid + s]);
        __syncthreads();
    }
    mx = red[0]; __syncthreads();

    float sum = 0.0f;
    for (int c2 = 0; c2 < cnt; c2++) { v[c2] = __expf(v[c2] - mx); sum += v[c2]; }
    red[tid] = sum; __syncthreads();
    #pragma unroll
    for (int s = 128; s > 0; s >>= 1) {
        if (tid < s) red[tid] += red[tid + s];
        __syncthreads();
    }
    const float inv = 1.0f / red[0];
    cnt = 0;
    for (int j = tid; j < n; j += 256) {
        float p = v[cnt++] * inv;
        bf16 hi, lo;
        split1(p, hi, lo);
        rh[j] = hi;
        rl[j] = lo;
    }
}

// ---------------- final octonion contraction --------------------------------
__global__ __launch_bounds__(256) void y_contract(
    const float* __restrict__ qh, const float* __restrict__ z,
    bf16* __restrict__ yph, bf16* __restrict__ ypl)
{
    const int gid = blockIdx.x * blockDim.x + threadIdx.x;
    const int t = gid >> 7;
    const int r = gid & 127;
    const int h = r >> 3;
    const int m = r & 7;

    const float* u_ptr = qh + ((size_t)h * T_SEQ + t) * HD + m * 8;
    const float* zr = z + ((size_t)h * T_SEQ + t) * KVW + m * 64;

    float u[8];
    #pragma unroll
    for (int i = 0; i < 8; i++) u[i] = u_ptr[i];

    float y[8] = {};
    #pragma unroll
    for (int p = 0; p < 8; p++) {
        float ep[8] = {};
        ep[p] = 1.0f;
        float w[8];
        omul_d(u, ep, w);
        float zp[8];
        #pragma unroll
        for (int q = 0; q < 8; q++) zp[q] = zr[p * 8 + q];
        float tt[8];
        omul_d(w, zp, tt);
        #pragma unroll
        for (int k = 0; k < 8; k++) y[k] += tt[k];
    }
    const size_t ob = (size_t)t * NE + h * 64 + m * 8;
    #pragma unroll
    for (int k = 0; k < 8; k++) {
        bf16 hi, lo;
        split1(y[k], hi, lo);
        yph[ob + k] = hi;
        ypl[ob + k] = lo;
    }
}

// ---------------- launch ----------------------------------------------------
extern "C" void kernel_launch(void* const* d_in, const int* in_sizes, int n_in,
                              void* d_out, int out_size)
{
    const float* x    = (const float*)d_in[0];
    const float* cosb = (const float*)d_in[1];
    const float* sinb = (const float*)d_in[2];
    const float* Wq   = (const float*)d_in[3];
    const float* Wk   = (const float*)d_in[4];
    const float* Wv   = (const float*)d_in[5];
    const float* Wo   = (const float*)d_in[6];
    float* out = (float*)d_out;

    float *qraw, *kraw, *vraw, *qh, *att, *z;
    bf16 *xh, *xl, *wqh, *wql, *wkh, *wkl, *wvh, *wvl, *woh, *wol;
    bf16 *qhh, *qhl, *khh, *khl, *kvh, *kvl, *atth, *attl, *yph, *ypl;
    cudaGetSymbolAddress((void**)&qraw, g_qraw);
    cudaGetSymbolAddress((void**)&kraw, g_kraw);
    cudaGetSymbolAddress((void**)&vraw, g_vraw);
    cudaGetSymbolAddress((void**)&qh,   g_qh);
    cudaGetSymbolAddress((void**)&att,  g_att);
    cudaGetSymbolAddress((void**)&z,    g_z);
    cudaGetSymbolAddress((void**)&xh,  g_xh);  cudaGetSymbolAddress((void**)&xl,  g_xl);
    cudaGetSymbolAddress((void**)&wqh, g_wqh); cudaGetSymbolAddress((void**)&wql, g_wql);
    cudaGetSymbolAddress((void**)&wkh, g_wkh); cudaGetSymbolAddress((void**)&wkl, g_wkl);
    cudaGetSymbolAddress((void**)&wvh, g_wvh); cudaGetSymbolAddress((void**)&wvl, g_wvl);
    cudaGetSymbolAddress((void**)&woh, g_woh); cudaGetSymbolAddress((void**)&wol, g_wol);
    cudaGetSymbolAddress((void**)&qhh, g_qhh); cudaGetSymbolAddress((void**)&qhl, g_qhl);
    cudaGetSymbolAddress((void**)&khh, g_khh); cudaGetSymbolAddress((void**)&khl, g_khl);
    cudaGetSymbolAddress((void**)&kvh, g_kvh); cudaGetSymbolAddress((void**)&kvl, g_kvl);
    cudaGetSymbolAddress((void**)&atth, g_atth); cudaGetSymbolAddress((void**)&attl, g_attl);
    cudaGetSymbolAddress((void**)&yph, g_yph); cudaGetSymbolAddress((void**)&ypl, g_ypl);

    const size_t sQK  = (size_t)T_SEQ * HD;
    const size_t sAtt = (size_t)T_SEQ * T_SEQ;

    // 0: split inputs / weights into bf16 hi/lo planes
    const int nx = T_SEQ * NE, nw = NE * NE;
    split_f32<<<(nx/2 + 255)/256, 256>>>(x,  xh,  xl,  nx);
    split_f32<<<(nw/2 + 255)/256, 256>>>(Wq, wqh, wql, nw);
    split_f32<<<(nw/2 + 255)/256, 256>>>(Wk, wkh, wkl, nw);
    split_f32<<<(nw/2 + 255)/256, 256>>>(Wv, wvh, wvl, nw);
    split_f32<<<(nw/2 + 255)/256, 256>>>(Wo, woh, wol, nw);

    // 1-3: QKV projections
    dim3 gproj(NE / 64, T_SEQ / 128, 1);
    bf_nt<<<gproj, 256>>>(xh, xl, wqh, wql, qraw, T_SEQ, NE, NE, 0, 0, 0, 1.0f, 0);
    bf_nt<<<gproj, 256>>>(xh, xl, wkh, wkl, kraw, T_SEQ, NE, NE, 0, 0, 0, 1.0f, 0);
    bf_nt<<<gproj, 256>>>(xh, xl, wvh, wvl, vraw, T_SEQ, NE, NE, 0, 0, 0, 1.0f, 0);

    // 4: rope + rms + octonion conj/unit + KV outer (writes bf16 planes)
    rope_rms_kv<<<T_SEQ, 512>>>(qraw, kraw, vraw, cosb, sinb,
                                qh, qhh, qhl, khh, khl, kvh, kvl);

    // 5: scores = (qh @ kh^T) / 8 per head, causal block-skip
    dim3 gsc(T_SEQ / 64, T_SEQ / 128, NH);
    bf_nt<<<gsc, 256>>>(qhh, qhl, khh, khl, att, T_SEQ, T_SEQ, HD, sQK, sQK, sAtt, 0.125f, 1);

    // 6: softmax -> bf16 hi/lo prob planes
    softmax_rows<<<dim3(T_SEQ, NH), 256>>>(att, atth, attl);

    // 7: Z = probs @ KV (causal)
    dim3 gz(KVW / 64, T_SEQ / 128, NH);
    bf_z<<<gz, 256>>>(atth, attl, kvh, kvl, z);

    // 8: octonion contraction -> ypre bf16 planes
    y_contract<<<(T_SEQ * NH * 8) / 256, 256>>>(qh, z, yph, ypl);

    // 9: output projection
    dim3 gout(NE / 64, T_SEQ / 128, 1);
    bf_nt<<<gout, 256>>>(yph, ypl, woh, wol, out, T_SEQ, NE, NE, 0, 0, 0, 1.0f, 0);
}

// round 9
// speedup vs baseline: 2.4286x; 1.4396x over previous
#include <cuda_runtime.h>
#include <cuda_bf16.h>
#include <math.h>

#define T_SEQ 2048
#define NH 16
#define HD 64
#define NE 1024
#define KVW 512

typedef __nv_bfloat16 bf16;

// ---------------- scratch (static device globals) ---------------------------
__device__ float g_qraw[(size_t)T_SEQ * NE];
__device__ float g_kraw[(size_t)T_SEQ * NE];
__device__ float g_vraw[(size_t)T_SEQ * NE];
__device__ float g_qh[(size_t)NH * T_SEQ * HD];      // fp32 for y_contract
__device__ float g_att[(size_t)NH * T_SEQ * T_SEQ];  // fp32 scores
__device__ float g_z[(size_t)NH * T_SEQ * KVW];

// bf16 hi/lo planes
__device__ bf16 g_xh[(size_t)T_SEQ * NE],  g_xl[(size_t)T_SEQ * NE];
__device__ bf16 g_wqh[(size_t)NE * NE],    g_wql[(size_t)NE * NE];
__device__ bf16 g_wkh[(size_t)NE * NE],    g_wkl[(size_t)NE * NE];
__device__ bf16 g_wvh[(size_t)NE * NE],    g_wvl[(size_t)NE * NE];
__device__ bf16 g_woh[(size_t)NE * NE],    g_wol[(size_t)NE * NE];
__device__ bf16 g_qhh[(size_t)NH * T_SEQ * HD],  g_qhl[(size_t)NH * T_SEQ * HD];
__device__ bf16 g_khh[(size_t)NH * T_SEQ * HD],  g_khl[(size_t)NH * T_SEQ * HD];
__device__ bf16 g_kvh[(size_t)NH * T_SEQ * KVW], g_kvl[(size_t)NH * T_SEQ * KVW];
__device__ bf16 g_atth[(size_t)NH * T_SEQ * T_SEQ], g_attl[(size_t)NH * T_SEQ * T_SEQ];
__device__ bf16 g_yph[(size_t)T_SEQ * NE], g_ypl[(size_t)T_SEQ * NE];

// ---------------- helpers ----------------------------------------------------
__device__ __forceinline__ unsigned smem_u32(const void* p) {
    return (unsigned)__cvta_generic_to_shared(p);
}
#define CPA16(dst_u32, src_ptr) \
    asm volatile("cp.async.cg.shared.global [%0], [%1], 16;" :: "r"(dst_u32), "l"(src_ptr))
#define CPCOMMIT() asm volatile("cp.async.commit_group;")
#define CPWAIT1()  asm volatile("cp.async.wait_group 1;")
#define CPWAIT0()  asm volatile("cp.async.wait_group 0;")

__device__ __forceinline__ void mma16(float* d, const unsigned* a, const unsigned* b) {
    asm volatile(
        "mma.sync.aligned.m16n8k16.row.col.f32.bf16.bf16.f32 "
        "{%0,%1,%2,%3},{%4,%5,%6,%7},{%8,%9},{%0,%1,%2,%3};"
        : "+f"(d[0]), "+f"(d[1]), "+f"(d[2]), "+f"(d[3])
        : "r"(a[0]), "r"(a[1]), "r"(a[2]), "r"(a[3]), "r"(b[0]), "r"(b[1]));
}
__device__ __forceinline__ void ldsm4(unsigned* r, unsigned a) {
    asm volatile("ldmatrix.sync.aligned.m8n8.x4.shared.b16 {%0,%1,%2,%3}, [%4];"
        : "=r"(r[0]), "=r"(r[1]), "=r"(r[2]), "=r"(r[3]) : "r"(a));
}
__device__ __forceinline__ void ldsm4t(unsigned* r, unsigned a) {
    asm volatile("ldmatrix.sync.aligned.m8n8.x4.trans.shared.b16 {%0,%1,%2,%3}, [%4];"
        : "=r"(r[0]), "=r"(r[1]), "=r"(r[2]), "=r"(r[3]) : "r"(a));
}
__device__ __forceinline__ void split2(float x0, float x1, unsigned& hi, unsigned& lo) {
    __nv_bfloat162 h = __floats2bfloat162_rn(x0, x1);
    hi = *reinterpret_cast<unsigned*>(&h);
    float2 hf = __bfloat1622float2(h);
    __nv_bfloat162 l = __floats2bfloat162_rn(x0 - hf.x, x1 - hf.y);
    lo = *reinterpret_cast<unsigned*>(&l);
}
__device__ __forceinline__ void split1(float x, bf16& hi, bf16& lo) {
    hi = __float2bfloat16(x);
    lo = __float2bfloat16(x - __bfloat162float(hi));
}

// ---------------- split kernel ----------------------------------------------
__global__ __launch_bounds__(256) void split_f32(
    const float* __restrict__ s, bf16* __restrict__ h, bf16* __restrict__ l, int n)
{
    int i = (blockIdx.x * 256 + threadIdx.x) * 2;
    if (i < n) {
        float2 v = *(const float2*)&s[i];
        unsigned hh, ll;
        split2(v.x, v.y, hh, ll);
        *(unsigned*)&h[i] = hh;
        *(unsigned*)&l[i] = ll;
    }
}

// ---------------- octonion helpers ------------------------------------------
__device__ __forceinline__ void qmul_d(const float* a, const float* b, float* r) {
    r[0] = a[0]*b[0] - a[1]*b[1] - a[2]*b[2] - a[3]*b[3];
    r[1] = a[0]*b[1] + a[1]*b[0] + a[2]*b[3] - a[3]*b[2];
    r[2] = a[0]*b[2] - a[1]*b[3] + a[2]*b[0] + a[3]*b[1];
    r[3] = a[0]*b[3] + a[1]*b[2] - a[2]*b[1] + a[3]*b[0];
}
__device__ __forceinline__ void omul_d(const float* x, const float* y, float* r) {
    float a[4] = {x[0], x[1], x[2], x[3]};
    float b[4] = {x[4], x[5], x[6], x[7]};
    float c[4] = {y[0], y[1], y[2], y[3]};
    float d[4] = {y[4], y[5], y[6], y[7]};
    float dc[4] = { d[0], -d[1], -d[2], -d[3] };
    float cc[4] = { c[0], -c[1], -c[2], -c[3] };
    float t1[4], t2[4], t3[4], t4[4];
    qmul_d(a,  c,  t1);
    qmul_d(dc, b,  t2);
    qmul_d(d,  a,  t3);
    qmul_d(b,  cc, t4);
    #pragma unroll
    for (int i = 0; i < 4; i++) { r[i]   = t1[i] - t2[i]; }
    #pragma unroll
    for (int i = 0; i < 4; i++) { r[4+i] = t3[i] + t4[i]; }
}

// ============================================================================
// bf16-plane MMA GEMM (NT): C[M,N] = alpha * (Ah+Al)[M,K] @ (Bh+Bl)[N,K]^T
// BM=128, BN=128, BK=32, 256 threads (8 warps 4m x 2n), warp tile 32x64.
// ============================================================================
__global__ __launch_bounds__(256) void bf_nt(
    const bf16* __restrict__ Ah, const bf16* __restrict__ Al,
    const bf16* __restrict__ Bh, const bf16* __restrict__ Bl,
    float* __restrict__ C,
    int M, int N, int K, size_t sA, size_t sB, size_t sC, float alpha, int causal)
{
    const int m0 = blockIdx.y * 128;
    const int n0 = blockIdx.x * 128;
    if (causal && n0 > m0 + 127) return;
    Ah += (size_t)blockIdx.z * sA;  Al += (size_t)blockIdx.z * sA;
    Bh += (size_t)blockIdx.z * sB;  Bl += (size_t)blockIdx.z * sB;
    C  += (size_t)blockIdx.z * sC;

    __shared__ __align__(16) bf16 As[2][2][128][40];  // [buf][plane][m][k] pad8
    __shared__ __align__(16) bf16 Bs[2][2][128][40];  // [buf][plane][n][k] pad8

    const int tid  = threadIdx.x;
    const int warp = tid >> 5, lane = tid & 31;
    const int wm = (warp >> 1) * 32, wn = (warp & 1) * 64;

    const int arow = tid >> 2;        // 0..63
    const int akc  = (tid & 3) * 8;   // 8 bf16 = 16B

    float acc[2][8][4] = {};

    const bf16* Ap[2] = {Ah, Al};
    const bf16* Bp[2] = {Bh, Bl};

    #pragma unroll
    for (int p = 0; p < 2; p++) {
        CPA16(smem_u32(&As[0][p][arow][akc]),      &Ap[p][(size_t)(m0 + arow)      * K + akc]);
        CPA16(smem_u32(&As[0][p][arow + 64][akc]), &Ap[p][(size_t)(m0 + arow + 64) * K + akc]);
        CPA16(smem_u32(&Bs[0][p][arow][akc]),      &Bp[p][(size_t)(n0 + arow)      * K + akc]);
        CPA16(smem_u32(&Bs[0][p][arow + 64][akc]), &Bp[p][(size_t)(n0 + arow + 64) * K + akc]);
    }
    CPCOMMIT();

    int buf = 0;
    for (int k0 = 0; k0 < K; k0 += 32) {
        if (k0 + 32 < K) {
            const int kn = k0 + 32;
            #pragma unroll
            for (int p = 0; p < 2; p++) {
                CPA16(smem_u32(&As[buf ^ 1][p][arow][akc]),      &Ap[p][(size_t)(m0 + arow)      * K + kn + akc]);
                CPA16(smem_u32(&As[buf ^ 1][p][arow + 64][akc]), &Ap[p][(size_t)(m0 + arow + 64) * K + kn + akc]);
                CPA16(smem_u32(&Bs[buf ^ 1][p][arow][akc]),      &Bp[p][(size_t)(n0 + arow)      * K + kn + akc]);
                CPA16(smem_u32(&Bs[buf ^ 1][p][arow + 64][akc]), &Bp[p][(size_t)(n0 + arow + 64) * K + kn + akc]);
            }
            CPCOMMIT();
            CPWAIT1();
        } else {
            CPWAIT0();
        }
        __syncthreads();

        #pragma unroll
        for (int kk = 0; kk < 32; kk += 16) {
            unsigned b_h[16], b_l[16];
            {
                const int br = wn + (lane & 7) + ((lane >> 4) << 3);
                const int bc = kk + (((lane >> 3) & 1) << 3);
                ldsm4(&b_h[0],  smem_u32(&Bs[buf][0][br][bc]));
                ldsm4(&b_l[0],  smem_u32(&Bs[buf][1][br][bc]));
                ldsm4(&b_h[4],  smem_u32(&Bs[buf][0][br + 16][bc]));
                ldsm4(&b_l[4],  smem_u32(&Bs[buf][1][br + 16][bc]));
                ldsm4(&b_h[8],  smem_u32(&Bs[buf][0][br + 32][bc]));
                ldsm4(&b_l[8],  smem_u32(&Bs[buf][1][br + 32][bc]));
                ldsm4(&b_h[12], smem_u32(&Bs[buf][0][br + 48][bc]));
                ldsm4(&b_l[12], smem_u32(&Bs[buf][1][br + 48][bc]));
            }
            #pragma unroll
            for (int mi = 0; mi < 2; mi++) {
                unsigned a_h[4], a_l[4];
                ldsm4(a_h, smem_u32(&As[buf][0][wm + mi*16 + (lane & 15)][kk + ((lane >> 4) << 3)]));
                ldsm4(a_l, smem_u32(&As[buf][1][wm + mi*16 + (lane & 15)][kk + ((lane >> 4) << 3)]));
                #pragma unroll
                for (int ni = 0; ni < 8; ni++) {
                    mma16(acc[mi][ni], a_h, &b_h[ni*2]);
                    mma16(acc[mi][ni], a_h, &b_l[ni*2]);
                    mma16(acc[mi][ni], a_l, &b_h[ni*2]);
                }
            }
        }
        __syncthreads();
        buf ^= 1;
    }

    const int g = lane >> 2, t = lane & 3;
    #pragma unroll
    for (int mi = 0; mi < 2; mi++)
        #pragma unroll
        for (int ni = 0; ni < 8; ni++) {
            const int row = m0 + wm + mi * 16 + g;
            const int col = n0 + wn + ni * 8 + 2 * t;
            float2 v0 = make_float2(alpha * acc[mi][ni][0], alpha * acc[mi][ni][1]);
            float2 v1 = make_float2(alpha * acc[mi][ni][2], alpha * acc[mi][ni][3]);
            *(float2*)&C[(size_t)row * N + col]       = v0;
            *(float2*)&C[(size_t)(row + 8) * N + col] = v1;
        }
}

// ============================================================================
// z-GEMM (NN, causal): z[h] = att[h](j<=i) @ kv[h]; bf16 planes, trans LDSM B.
// BM=256, BN=128, BK=32, 512 threads (16 warps 4m x 4n), warp tile 64x32.
// ============================================================================
__global__ __launch_bounds__(512) void bf_z(
    const bf16* __restrict__ Ahh, const bf16* __restrict__ All,
    const bf16* __restrict__ Bhh, const bf16* __restrict__ Bll,
    float* __restrict__ z)
{
    const int h  = blockIdx.z;
    const int m0 = blockIdx.y * 256;
    const int n0 = blockIdx.x * 128;
    const bf16* Ap[2] = { Ahh + (size_t)h * T_SEQ * T_SEQ, All + (size_t)h * T_SEQ * T_SEQ };
    const bf16* Bp[2] = { Bhh + (size_t)h * T_SEQ * KVW,  Bll + (size_t)h * T_SEQ * KVW };
    float* C = z + (size_t)h * T_SEQ * KVW;
    const int Kend = m0 + 256;

    __shared__ __align__(16) bf16 As[2][2][256][40];  // [buf][plane][m][k] pad8
    __shared__ __align__(16) bf16 Bs[2][2][32][136];  // [buf][plane][k][n] pad8

    const int tid  = threadIdx.x;
    const int warp = tid >> 5, lane = tid & 31;
    const int wm = (warp >> 2) * 64, wn = (warp & 3) * 32;

    const int arow = tid >> 2;        // 0..127
    const int akc  = (tid & 3) * 8;
    const int bkr  = tid >> 4;        // 0..31
    const int bnc  = (tid & 15) * 8;  // 0..120

    float acc[4][4][4] = {};

    #pragma unroll
    for (int p = 0; p < 2; p++) {
        CPA16(smem_u32(&As[0][p][arow][akc]),       &Ap[p][(size_t)(m0 + arow)       * T_SEQ + akc]);
        CPA16(smem_u32(&As[0][p][arow + 128][akc]), &Ap[p][(size_t)(m0 + arow + 128) * T_SEQ + akc]);
        CPA16(smem_u32(&Bs[0][p][bkr][bnc]),        &Bp[p][(size_t)bkr * KVW + n0 + bnc]);
    }
    CPCOMMIT();

    const bf16 z0 = __float2bfloat16(0.0f);

    int buf = 0;
    for (int k0 = 0; k0 < Kend; k0 += 32) {
        if (k0 + 32 < Kend) {
            const int kn = k0 + 32;
            #pragma unroll
            for (int p = 0; p < 2; p++) {
                CPA16(smem_u32(&As[buf ^ 1][p][arow][akc]),       &Ap[p][(size_t)(m0 + arow)       * T_SEQ + kn + akc]);
                CPA16(smem_u32(&As[buf ^ 1][p][arow + 128][akc]), &Ap[p][(size_t)(m0 + arow + 128) * T_SEQ + kn + akc]);
                CPA16(smem_u32(&Bs[buf ^ 1][p][bkr][bnc]),        &Bp[p][(size_t)(kn + bkr) * KVW + n0 + bnc]);
            }
            CPCOMMIT();
            CPWAIT1();
        } else {
            CPWAIT0();
        }
        __syncthreads();

        if (k0 >= m0) {  // diagonal band: zero above-diagonal A entries
            const int row = tid >> 1;            // 0..255
            const int i   = m0 + row;
            const int cb  = (tid & 1) * 16;
            #pragma unroll
            for (int c = 0; c < 16; c++) {
                if (k0 + cb + c > i) {
                    As[buf][0][row][cb + c] = z0;
                    As[buf][1][row][cb + c] = z0;
                }
            }
            __syncthreads();
        }

        #pragma unroll
        for (int kk = 0; kk < 32; kk += 16) {
            unsigned b_h[8], b_l[8];
            {
                const int kr = kk + (lane & 7) + (((lane >> 3) & 1) << 3);
                const int nc = wn + ((lane >> 4) << 3);
                ldsm4t(&b_h[0], smem_u32(&Bs[buf][0][kr][nc]));
                ldsm4t(&b_l[0], smem_u32(&Bs[buf][1][kr][nc]));
                ldsm4t(&b_h[4], smem_u32(&Bs[buf][0][kr][nc + 16]));
                ldsm4t(&b_l[4], smem_u32(&Bs[buf][1][kr][nc + 16]));
            }
            #pragma unroll
            for (int mi = 0; mi < 4; mi++) {
                unsigned a_h[4], a_l[4];
                ldsm4(a_h, smem_u32(&As[buf][0][wm + mi*16 + (lane & 15)][kk + ((lane >> 4) << 3)]));
                ldsm4(a_l, smem_u32(&As[buf][1][wm + mi*16 + (lane & 15)][kk + ((lane >> 4) << 3)]));
                #pragma unroll
                for (int ni = 0; ni < 4; ni++) {
                    mma16(acc[mi][ni], a_h, &b_h[ni*2]);
                    mma16(acc[mi][ni], a_h, &b_l[ni*2]);
                    mma16(acc[mi][ni], a_l, &b_h[ni*2]);
                }
            }
        }
        __syncthreads();
        buf ^= 1;
    }

    const int g = lane >> 2, t = lane & 3;
    #pragma unroll
    for (int mi = 0; mi < 4; mi++)
        #pragma unroll
        for (int ni = 0; ni < 4; ni++) {
            const int row = m0 + wm + mi * 16 + g;
            const int col = n0 + wn + ni * 8 + 2 * t;
            float2 v0 = make_float2(acc[mi][ni][0], acc[mi][ni][1]);
            float2 v1 = make_float2(acc[mi][ni][2], acc[mi][ni][3]);
            *(float2*)&C[(size_t)row * KVW + col]       = v0;
            *(float2*)&C[(size_t)(row + 8) * KVW + col] = v1;
        }
}

// ---------------- fused RoPE + RMS + octonion conj-unit + KV outer ----------
__global__ __launch_bounds__(512) void rope_rms_kv(
    const float* __restrict__ qraw, const float* __restrict__ kraw,
    const float* __restrict__ vraw, const float* __restrict__ cosb,
    const float* __restrict__ sinb,
    float* __restrict__ qh,
    bf16* __restrict__ qhh, bf16* __restrict__ qhl,
    bf16* __restrict__ khh, bf16* __restrict__ khl,
    bf16* __restrict__ kvh, bf16* __restrict__ kvl)
{
    const int t = blockIdx.x;
    const int h = threadIdx.x >> 5;
    const int lane = threadIdx.x & 31;
    const unsigned FULL = 0xffffffffu;

    const float c = cosb[t * 32 + lane];
    const float s = sinb[t * 32 + lane];
    const size_t base = (size_t)t * NE + (size_t)h * HD;
    float q1 = qraw[base + lane], q2 = qraw[base + lane + 32];
    float k1 = kraw[base + lane], k2 = kraw[base + lane + 32];
    float v1 = vraw[base + lane], v2 = vraw[base + lane + 32];

    float qr1 = q1 * c + q2 * s, qr2 = q2 * c - q1 * s;
    float kr1 = k1 * c + k2 * s, kr2 = k2 * c - k1 * s;

    float sq = qr1 * qr1 + qr2 * qr2;
    float sk = kr1 * kr1 + kr2 * kr2;
    #pragma unroll
    for (int off = 16; off > 0; off >>= 1) {
        sq += __shfl_xor_sync(FULL, sq, off);
        sk += __shfl_xor_sync(FULL, sk, off);
    }
    const float rq = rsqrtf(sq * (1.0f / 64.0f) + 1e-6f);
    const float rk = rsqrtf(sk * (1.0f / 64.0f) + 1e-6f);
    qr1 *= rq; qr2 *= rq;
    kr1 *= rk; kr2 *= rk;

    const size_t hb = ((size_t)h * T_SEQ + t) * HD;
    qh[hb + lane] = qr1; qh[hb + lane + 32] = qr2;
    {
        bf16 hi, lo;
        split1(qr1, hi, lo); qhh[hb + lane] = hi;      qhl[hb + lane] = lo;
        split1(qr2, hi, lo); qhh[hb + lane + 32] = hi; qhl[hb + lane + 32] = lo;
        split1(kr1, hi, lo); khh[hb + lane] = hi;      khl[hb + lane] = lo;
        split1(kr2, hi, lo); khh[hb + lane + 32] = hi; khl[hb + lane + 32] = lo;
    }

    float g1 = kr1 * kr1, g2 = kr2 * kr2;
    #pragma unroll
    for (int off = 1; off < 8; off <<= 1) {
        g1 += __shfl_xor_sync(FULL, g1, off);
        g2 += __shfl_xor_sync(FULL, g2, off);
    }
    const float sgn = ((lane & 7) == 0) ? 1.0f : -1.0f;
    const float kc1 = sgn * kr1 / fmaxf(sqrtf(g1), 1e-12f);
    const float kc2 = sgn * kr2 / fmaxf(sqrtf(g2), 1e-12f);

    __shared__ float skc[16][64];
    __shared__ float sv[16][64];
    skc[h][lane] = kc1; skc[h][lane + 32] = kc2;
    sv[h][lane]  = v1;  sv[h][lane + 32]  = v2;
    __syncwarp();

    const size_t kvb = ((size_t)h * T_SEQ + t) * KVW;
    #pragma unroll
    for (int r = 0; r < 16; r++) {
        int n = lane + 32 * r;
        int m = n >> 6, p = (n >> 3) & 7, q = n & 7;
        float val = skc[h][m * 8 + p] * sv[h][m * 8 + q];
        bf16 hi, lo;
        split1(val, hi, lo);
        kvh[kvb + n] = hi;
        kvl[kvb + n] = lo;
    }
}

// ---------------- softmax rows (causal length i+1) -> bf16 hi/lo planes -----
__global__ __launch_bounds__(256) void softmax_rows(
    const float* __restrict__ att, bf16* __restrict__ atth, bf16* __restrict__ attl)
{
    const int i = blockIdx.x;
    const int h = blockIdx.y;
    const float* row = att + (size_t)h * T_SEQ * T_SEQ + (size_t)i * T_SEQ;
    bf16* rh = atth + (size_t)h * T_SEQ * T_SEQ + (size_t)i * T_SEQ;
    bf16* rl = attl + (size_t)h * T_SEQ * T_SEQ + (size_t)i * T_SEQ;
    const int n = i + 1;
    const int tid = threadIdx.x;

    float v[8];
    int cnt = 0;
    float mx = -1e30f;
    for (int j = tid; j < n; j += 256) {
        float x = row[j];
        v[cnt++] = x;
        mx = fmaxf(mx, x);
    }
    __shared__ float red[256];
    red[tid] = mx; __syncthreads();
    #pragma unroll
    for (int s = 128; s > 0; s >>= 1) {
        if (tid < s) red[tid] = fmaxf(red[tid], red[tid + s]);
        __syncthreads();
    }
    mx = red[0]; __syncthreads();

    float sum = 0.0f;
    for (int c2 = 0; c2 < cnt; c2++) { v[c2] = __expf(v[c2] - mx); sum += v[c2]; }
    red[tid] = sum; __syncthreads();
    #pragma unroll
    for (int s = 128; s > 0; s >>= 1) {
        if (tid < s) red[tid] += red[tid + s];
        __syncthreads();
    }
    const float inv = 1.0f / red[0];
    cnt = 0;
    for (int j = tid; j < n; j += 256) {
        float p = v[cnt++] * inv;
        bf16 hi, lo;
        split1(p, hi, lo);
        rh[j] = hi;
        rl[j] = lo;
    }
}

// ---------------- final octonion contraction --------------------------------
__global__ __launch_bounds__(256) void y_contract(
    const float* __restrict__ qh, const float* __restrict__ z,
    bf16* __restrict__ yph, bf16* __restrict__ ypl)
{
    const int gid = blockIdx.x * blockDim.x + threadIdx.x;
    const int t = gid >> 7;
    const int r = gid & 127;
    const int h = r >> 3;
    const int m = r & 7;

    const float* u_ptr = qh + ((size_t)h * T_SEQ + t) * HD + m * 8;
    const float* zr = z + ((size_t)h * T_SEQ + t) * KVW + m * 64;

    float u[8];
    #pragma unroll
    for (int i = 0; i < 8; i++) u[i] = u_ptr[i];

    float y[8] = {};
    #pragma unroll
    for (int p = 0; p < 8; p++) {
        float ep[8] = {};
        ep[p] = 1.0f;
        float w[8];
        omul_d(u, ep, w);
        float zp[8];
        #pragma unroll
        for (int q = 0; q < 8; q++) zp[q] = zr[p * 8 + q];
        float tt[8];
        omul_d(w, zp, tt);
        #pragma unroll
        for (int k = 0; k < 8; k++) y[k] += tt[k];
    }
    const size_t ob = (size_t)t * NE + h * 64 + m * 8;
    #pragma unroll
    for (int k = 0; k < 8; k++) {
        bf16 hi, lo;
        split1(y[k], hi, lo);
        yph[ob + k] = hi;
        ypl[ob + k] = lo;
    }
}

// ---------------- launch ----------------------------------------------------
extern "C" void kernel_launch(void* const* d_in, const int* in_sizes, int n_in,
                              void* d_out, int out_size)
{
    const float* x    = (const float*)d_in[0];
    const float* cosb = (const float*)d_in[1];
    const float* sinb = (const float*)d_in[2];
    const float* Wq   = (const float*)d_in[3];
    const float* Wk   = (const float*)d_in[4];
    const float* Wv   = (const float*)d_in[5];
    const float* Wo   = (const float*)d_in[6];
    float* out = (float*)d_out;

    float *qraw, *kraw, *vraw, *qh, *att, *z;
    bf16 *xh, *xl, *wqh, *wql, *wkh, *wkl, *wvh, *wvl, *woh, *wol;
    bf16 *qhh, *qhl, *khh, *khl, *kvh, *kvl, *atth, *attl, *yph, *ypl;
    cudaGetSymbolAddress((void**)&qraw, g_qraw);
    cudaGetSymbolAddress((void**)&kraw, g_kraw);
    cudaGetSymbolAddress((void**)&vraw, g_vraw);
    cudaGetSymbolAddress((void**)&qh,   g_qh);
    cudaGetSymbolAddress((void**)&att,  g_att);
    cudaGetSymbolAddress((void**)&z,    g_z);
    cudaGetSymbolAddress((void**)&xh,  g_xh);  cudaGetSymbolAddress((void**)&xl,  g_xl);
    cudaGetSymbolAddress((void**)&wqh, g_wqh); cudaGetSymbolAddress((void**)&wql, g_wql);
    cudaGetSymbolAddress((void**)&wkh, g_wkh); cudaGetSymbolAddress((void**)&wkl, g_wkl);
    cudaGetSymbolAddress((void**)&wvh, g_wvh); cudaGetSymbolAddress((void**)&wvl, g_wvl);
    cudaGetSymbolAddress((void**)&woh, g_woh); cudaGetSymbolAddress((void**)&wol, g_wol);
    cudaGetSymbolAddress((void**)&qhh, g_qhh); cudaGetSymbolAddress((void**)&qhl, g_qhl);
    cudaGetSymbolAddress((void**)&khh, g_khh); cudaGetSymbolAddress((void**)&khl, g_khl);
    cudaGetSymbolAddress((void**)&kvh, g_kvh); cudaGetSymbolAddress((void**)&kvl, g_kvl);
    cudaGetSymbolAddress((void**)&atth, g_atth); cudaGetSymbolAddress((void**)&attl, g_attl);
    cudaGetSymbolAddress((void**)&yph, g_yph); cudaGetSymbolAddress((void**)&ypl, g_ypl);

    const size_t sQK  = (size_t)T_SEQ * HD;
    const size_t sAtt = (size_t)T_SEQ * T_SEQ;

    // 0: split inputs / weights into bf16 hi/lo planes
    const int nx = T_SEQ * NE, nw = NE * NE;
    split_f32<<<(nx/2 + 255)/256, 256>>>(x,  xh,  xl,  nx);
    split_f32<<<(nw/2 + 255)/256, 256>>>(Wq, wqh, wql, nw);
    split_f32<<<(nw/2 + 255)/256, 256>>>(Wk, wkh, wkl, nw);
    split_f32<<<(nw/2 + 255)/256, 256>>>(Wv, wvh, wvl, nw);
    split_f32<<<(nw/2 + 255)/256, 256>>>(Wo, woh, wol, nw);

    // 1-3: QKV projections
    dim3 gproj(NE / 128, T_SEQ / 128, 1);
    bf_nt<<<gproj, 256>>>(xh, xl, wqh, wql, qraw, T_SEQ, NE, NE, 0, 0, 0, 1.0f, 0);
    bf_nt<<<gproj, 256>>>(xh, xl, wkh, wkl, kraw, T_SEQ, NE, NE, 0, 0, 0, 1.0f, 0);
    bf_nt<<<gproj, 256>>>(xh, xl, wvh, wvl, vraw, T_SEQ, NE, NE, 0, 0, 0, 1.0f, 0);

    // 4: rope + rms + octonion conj/unit + KV outer (writes bf16 planes)
    rope_rms_kv<<<T_SEQ, 512>>>(qraw, kraw, vraw, cosb, sinb,
                                qh, qhh, qhl, khh, khl, kvh, kvl);

    // 5: scores = (qh @ kh^T) / 8 per head, causal block-skip
    dim3 gsc(T_SEQ / 128, T_SEQ / 128, NH);
    bf_nt<<<gsc, 256>>>(qhh, qhl, khh, khl, att, T_SEQ, T_SEQ, HD, sQK, sQK, sAtt, 0.125f, 1);

    // 6: softmax -> bf16 hi/lo prob planes
    softmax_rows<<<dim3(T_SEQ, NH), 256>>>(att, atth, attl);

    // 7: Z = probs @ KV (causal), BM=256 x BN=128 tiles
    dim3 gz(KVW / 128, T_SEQ / 256, NH);
    bf_z<<<gz, 512>>>(atth, attl, kvh, kvl, z);

    // 8: octonion contraction -> ypre bf16 planes
    y_contract<<<(T_SEQ * NH * 8) / 256, 256>>>(qh, z, yph, ypl);

    // 9: output projection
    dim3 gout(NE / 128, T_SEQ / 128, 1);
    bf_nt<<<gout, 256>>>(yph, ypl, woh, wol, out, T_SEQ, NE, NE, 0, 0, 0, 1.0f, 0);
}

// round 13
// speedup vs baseline: 2.6008x; 1.0709x over previous
#include <cuda_runtime.h>
#include <cuda_bf16.h>
#include <math.h>
#include <stdint.h>

#define T_SEQ 2048
#define NH 16
#define HD 64
#define NE 1024
#define KVW 512

typedef __nv_bfloat16 bf16;

// ---------------- scratch (static device globals) ---------------------------
__device__ float g_qraw[(size_t)T_SEQ * NE];
__device__ float g_kraw[(size_t)T_SEQ * NE];
__device__ float g_vraw[(size_t)T_SEQ * NE];
__device__ float g_qh[(size_t)NH * T_SEQ * HD];      // fp32 for epilogue contraction
__device__ float g_att[(size_t)NH * T_SEQ * T_SEQ];  // fp32 scores
__device__ bf16 g_xh[(size_t)T_SEQ * NE],  g_xl[(size_t)T_SEQ * NE];
__device__ bf16 g_wqh[(size_t)NE * NE],    g_wql[(size_t)NE * NE];
__device__ bf16 g_wkh[(size_t)NE * NE],    g_wkl[(size_t)NE * NE];
__device__ bf16 g_wvh[(size_t)NE * NE],    g_wvl[(size_t)NE * NE];
__device__ bf16 g_woh[(size_t)NE * NE],    g_wol[(size_t)NE * NE];
__device__ bf16 g_qhh[(size_t)NH * T_SEQ * HD],  g_qhl[(size_t)NH * T_SEQ * HD];
__device__ bf16 g_khh[(size_t)NH * T_SEQ * HD],  g_khl[(size_t)NH * T_SEQ * HD];
__device__ bf16 g_kvh[(size_t)NH * T_SEQ * KVW], g_kvl[(size_t)NH * T_SEQ * KVW];
__device__ bf16 g_atth[(size_t)NH * T_SEQ * T_SEQ], g_attl[(size_t)NH * T_SEQ * T_SEQ];
__device__ bf16 g_yph[(size_t)T_SEQ * NE], g_ypl[(size_t)T_SEQ * NE];

// ---------------- helpers ----------------------------------------------------
__device__ __forceinline__ unsigned smem_u32(const void* p) {
    return (unsigned)__cvta_generic_to_shared(p);
}
#define CPA16(dst_u32, src_ptr) \
    asm volatile("cp.async.cg.shared.global [%0], [%1], 16;" :: "r"(dst_u32), "l"(src_ptr))
#define CPCOMMIT() asm volatile("cp.async.commit_group;")
#define CPWAIT2()  asm volatile("cp.async.wait_group 2;")
#define CPWAIT1()  asm volatile("cp.async.wait_group 1;")
#define CPWAIT0()  asm volatile("cp.async.wait_group 0;")

__device__ __forceinline__ void mma16(float* d, const unsigned* a, const unsigned* b) {
    asm volatile(
        "mma.sync.aligned.m16n8k16.row.col.f32.bf16.bf16.f32 "
        "{%0,%1,%2,%3},{%4,%5,%6,%7},{%8,%9},{%0,%1,%2,%3};"
        : "+f"(d[0]), "+f"(d[1]), "+f"(d[2]), "+f"(d[3])
        : "r"(a[0]), "r"(a[1]), "r"(a[2]), "r"(a[3]), "r"(b[0]), "r"(b[1]));
}
__device__ __forceinline__ void ldsm4(unsigned* r, unsigned a) {
    asm volatile("ldmatrix.sync.aligned.m8n8.x4.shared.b16 {%0,%1,%2,%3}, [%4];"
        : "=r"(r[0]), "=r"(r[1]), "=r"(r[2]), "=r"(r[3]) : "r"(a));
}
__device__ __forceinline__ void ldsm4t(unsigned* r, unsigned a) {
    asm volatile("ldmatrix.sync.aligned.m8n8.x4.trans.shared.b16 {%0,%1,%2,%3}, [%4];"
        : "=r"(r[0]), "=r"(r[1]), "=r"(r[2]), "=r"(r[3]) : "r"(a));
}
__device__ __forceinline__ void split2(float x0, float x1, unsigned& hi, unsigned& lo) {
    __nv_bfloat162 h = __floats2bfloat162_rn(x0, x1);
    hi = *reinterpret_cast<unsigned*>(&h);
    float2 hf = __bfloat1622float2(h);
    __nv_bfloat162 l = __floats2bfloat162_rn(x0 - hf.x, x1 - hf.y);
    lo = *reinterpret_cast<unsigned*>(&l);
}
__device__ __forceinline__ void split1(float x, bf16& hi, bf16& lo) {
    hi = __float2bfloat16(x);
    lo = __float2bfloat16(x - __bfloat162float(hi));
}

// ---------------- split kernel ----------------------------------------------
__global__ __launch_bounds__(256) void split_f32(
    const float* __restrict__ s, bf16* __restrict__ h, bf16* __restrict__ l, int n)
{
    int i = (blockIdx.x * 256 + threadIdx.x) * 2;
    if (i < n) {
        float2 v = *(const float2*)&s[i];
        unsigned hh, ll;
        split2(v.x, v.y, hh, ll);
        *(unsigned*)&h[i] = hh;
        *(unsigned*)&l[i] = ll;
    }
}

// ---------------- octonion helpers ------------------------------------------
__device__ __forceinline__ void qmul_d(const float* a, const float* b, float* r) {
    r[0] = a[0]*b[0] - a[1]*b[1] - a[2]*b[2] - a[3]*b[3];
    r[1] = a[0]*b[1] + a[1]*b[0] + a[2]*b[3] - a[3]*b[2];
    r[2] = a[0]*b[2] - a[1]*b[3] + a[2]*b[0] + a[3]*b[1];
    r[3] = a[0]*b[3] + a[1]*b[2] - a[2]*b[1] + a[3]*b[0];
}
__device__ __forceinline__ void omul_d(const float* x, const float* y, float* r) {
    float a[4] = {x[0], x[1], x[2], x[3]};
    float b[4] = {x[4], x[5], x[6], x[7]};
    float c[4] = {y[0], y[1], y[2], y[3]};
    float d[4] = {y[4], y[5], y[6], y[7]};
    float dc[4] = { d[0], -d[1], -d[2], -d[3] };
    float cc[4] = { c[0], -c[1], -c[2], -c[3] };
    float t1[4], t2[4], t3[4], t4[4];
    qmul_d(a,  c,  t1);
    qmul_d(dc, b,  t2);
    qmul_d(d,  a,  t3);
    qmul_d(b,  cc, t4);
    #pragma unroll
    for (int i = 0; i < 4; i++) { r[i]   = t1[i] - t2[i]; }
    #pragma unroll
    for (int i = 0; i < 4; i++) { r[4+i] = t3[i] + t4[i]; }
}

// ============================================================================
// bf16-plane legacy MMA GEMM (NT): C = alpha * (Ah+Al) @ (Bh+Bl)^T
// BM=128, BN=128, BK=32, 256 threads (8 warps 4m x 2n), warp tile 32x64.
// ============================================================================
__global__ __launch_bounds__(256) void bf_nt(
    const bf16* __restrict__ Ah, const bf16* __restrict__ Al,
    const bf16* __restrict__ Bh, const bf16* __restrict__ Bl,
    float* __restrict__ C,
    int M, int N, int K, size_t sA, size_t sB, size_t sC, float alpha, int causal)
{
    const int m0 = blockIdx.y * 128;
    const int n0 = blockIdx.x * 128;
    if (causal && n0 > m0 + 127) return;
    Ah += (size_t)blockIdx.z * sA;  Al += (size_t)blockIdx.z * sA;
    Bh += (size_t)blockIdx.z * sB;  Bl += (size_t)blockIdx.z * sB;
    C  += (size_t)blockIdx.z * sC;

    __shared__ __align__(16) bf16 As[2][2][128][40];
    __shared__ __align__(16) bf16 Bs[2][2][128][40];

    const int tid  = threadIdx.x;
    const int warp = tid >> 5, lane = tid & 31;
    const int wm = (warp >> 1) * 32, wn = (warp & 1) * 64;

    const int arow = tid >> 2;
    const int akc  = (tid & 3) * 8;

    float acc[2][8][4] = {};

    const bf16* Ap[2] = {Ah, Al};
    const bf16* Bp[2] = {Bh, Bl};

    #pragma unroll
    for (int p = 0; p < 2; p++) {
        CPA16(smem_u32(&As[0][p][arow][akc]),      &Ap[p][(size_t)(m0 + arow)      * K + akc]);
        CPA16(smem_u32(&As[0][p][arow + 64][akc]), &Ap[p][(size_t)(m0 + arow + 64) * K + akc]);
        CPA16(smem_u32(&Bs[0][p][arow][akc]),      &Bp[p][(size_t)(n0 + arow)      * K + akc]);
        CPA16(smem_u32(&Bs[0][p][arow + 64][akc]), &Bp[p][(size_t)(n0 + arow + 64) * K + akc]);
    }
    CPCOMMIT();

    int buf = 0;
    for (int k0 = 0; k0 < K; k0 += 32) {
        if (k0 + 32 < K) {
            const int kn = k0 + 32;
            #pragma unroll
            for (int p = 0; p < 2; p++) {
                CPA16(smem_u32(&As[buf ^ 1][p][arow][akc]),      &Ap[p][(size_t)(m0 + arow)      * K + kn + akc]);
                CPA16(smem_u32(&As[buf ^ 1][p][arow + 64][akc]), &Ap[p][(size_t)(m0 + arow + 64) * K + kn + akc]);
                CPA16(smem_u32(&Bs[buf ^ 1][p][arow][akc]),      &Bp[p][(size_t)(n0 + arow)      * K + kn + akc]);
                CPA16(smem_u32(&Bs[buf ^ 1][p][arow + 64][akc]), &Bp[p][(size_t)(n0 + arow + 64) * K + kn + akc]);
            }
            CPCOMMIT();
            CPWAIT1();
        } else {
            CPWAIT0();
        }
        __syncthreads();

        #pragma unroll
        for (int kk = 0; kk < 32; kk += 16) {
            unsigned b_h[16], b_l[16];
            {
                const int br = wn + (lane & 7) + ((lane >> 4) << 3);
                const int bc = kk + (((lane >> 3) & 1) << 3);
                ldsm4(&b_h[0],  smem_u32(&Bs[buf][0][br][bc]));
                ldsm4(&b_l[0],  smem_u32(&Bs[buf][1][br][bc]));
                ldsm4(&b_h[4],  smem_u32(&Bs[buf][0][br + 16][bc]));
                ldsm4(&b_l[4],  smem_u32(&Bs[buf][1][br + 16][bc]));
                ldsm4(&b_h[8],  smem_u32(&Bs[buf][0][br + 32][bc]));
                ldsm4(&b_l[8],  smem_u32(&Bs[buf][1][br + 32][bc]));
                ldsm4(&b_h[12], smem_u32(&Bs[buf][0][br + 48][bc]));
                ldsm4(&b_l[12], smem_u32(&Bs[buf][1][br + 48][bc]));
            }
            #pragma unroll
            for (int mi = 0; mi < 2; mi++) {
                unsigned a_h[4], a_l[4];
                ldsm4(a_h, smem_u32(&As[buf][0][wm + mi*16 + (lane & 15)][kk + ((lane >> 4) << 3)]));
                ldsm4(a_l, smem_u32(&As[buf][1][wm + mi*16 + (lane & 15)][kk + ((lane >> 4) << 3)]));
                #pragma unroll
                for (int ni = 0; ni < 8; ni++) {
                    mma16(acc[mi][ni], a_h, &b_h[ni*2]);
                    mma16(acc[mi][ni], a_h, &b_l[ni*2]);
                    mma16(acc[mi][ni], a_l, &b_h[ni*2]);
                }
            }
        }
        __syncthreads();
        buf ^= 1;
    }

    const int g = lane >> 2, t = lane & 3;
    #pragma unroll
    for (int mi = 0; mi < 2; mi++)
        #pragma unroll
        for (int ni = 0; ni < 8; ni++) {
            const int row = m0 + wm + mi * 16 + g;
            const int col = n0 + wn + ni * 8 + 2 * t;
            float2 v0 = make_float2(alpha * acc[mi][ni][0], alpha * acc[mi][ni][1]);
            float2 v1 = make_float2(alpha * acc[mi][ni][2], alpha * acc[mi][ni][3]);
            *(float2*)&C[(size_t)row * N + col]       = v0;
            *(float2*)&C[(size_t)(row + 8) * N + col] = v1;
        }
}

// ============================================================================
// z-GEMM + fused octonion contraction.
// z[h] = att[h](j<=i) @ kv[h], then y = sum_p (u o e_p) o Z_p per (row, group).
// BM=256, BN=128, BK=32, 512 threads (16 warps 4m x 4n), warp tile 64x32.
// 3-stage cp.async pipeline, dynamic smem. Causal band pre-zeroed by softmax.
// Outputs yph/ypl bf16 planes directly (no z materialization).
// ============================================================================
#define ZA_STRIDE 40
#define ZB_STRIDE 136
#define ZA_BYTES (256 * ZA_STRIDE * 2)                 // 20480 per (stage,plane)
#define ZB_BASE  (6 * ZA_BYTES)                        // 122880
#define ZB_BYTES (32 * ZB_STRIDE * 2)                  // 8704
#define ZSMEM    (ZB_BASE + 6 * ZB_BYTES)              // 175104

__global__ void __launch_bounds__(512) bf_z(
    const bf16* __restrict__ Ahh, const bf16* __restrict__ All,
    const bf16* __restrict__ Bhh, const bf16* __restrict__ Bll,
    const float* __restrict__ qh,
    bf16* __restrict__ yph, bf16* __restrict__ ypl)
{
    extern __shared__ __align__(16) char dsm[];
    const int h  = blockIdx.z;
    const int m0 = blockIdx.y * 256;
    const int n0 = blockIdx.x * 128;
    const bf16* Ap[2] = { Ahh + (size_t)h * T_SEQ * T_SEQ, All + (size_t)h * T_SEQ * T_SEQ };
    const bf16* Bp[2] = { Bhh + (size_t)h * T_SEQ * KVW,  Bll + (size_t)h * T_SEQ * KVW };
    const int nk = m0 / 32 + 8;   // K tiles of 32 up to Kend = m0+256

    const int tid  = threadIdx.x;
    const int warp = tid >> 5, lane = tid & 31;
    const int wm = (warp >> 2) * 64, wn = (warp & 3) * 32;

    const int arow = tid >> 2;        // 0..127
    const int akc  = (tid & 3) * 8;
    const int bkr  = tid >> 4;        // 0..31
    const int bnc  = (tid & 15) * 8;  // 0..120

    float acc[4][4][4] = {};

    #define ZA_PTR(s, p, r, c) ((bf16*)(dsm + ((s) * 2 + (p)) * ZA_BYTES) + (r) * ZA_STRIDE + (c))
    #define ZB_PTR(s, p, r, c) ((bf16*)(dsm + ZB_BASE + ((s) * 2 + (p)) * ZB_BYTES) + (r) * ZB_STRIDE + (c))

    auto load_stage = [&](int s, int k0) {
        #pragma unroll
        for (int p = 0; p < 2; p++) {
            CPA16(smem_u32(ZA_PTR(s, p, arow, akc)),       &Ap[p][(size_t)(m0 + arow)       * T_SEQ + k0 + akc]);
            CPA16(smem_u32(ZA_PTR(s, p, arow + 128, akc)), &Ap[p][(size_t)(m0 + arow + 128) * T_SEQ + k0 + akc]);
            CPA16(smem_u32(ZB_PTR(s, p, bkr, bnc)),        &Bp[p][(size_t)(k0 + bkr) * KVW + n0 + bnc]);
        }
    };

    load_stage(0, 0);  CPCOMMIT();
    load_stage(1, 32); CPCOMMIT();

    for (int kt = 0; kt < nk; kt++) {
        const int st = kt % 3;
        if (kt + 2 < nk) load_stage((kt + 2) % 3, (kt + 2) * 32);
        CPCOMMIT();
        CPWAIT2();           // stage kt has landed
        __syncthreads();

        #pragma unroll
        for (int kk = 0; kk < 32; kk += 16) {
            unsigned b_h[8], b_l[8];
            {
                const int kr = kk + (lane & 7) + (((lane >> 3) & 1) << 3);
                const int nc = wn + ((lane >> 4) << 3);
                ldsm4t(&b_h[0], smem_u32(ZB_PTR(st, 0, kr, nc)));
                ldsm4t(&b_l[0], smem_u32(ZB_PTR(st, 1, kr, nc)));
                ldsm4t(&b_h[4], smem_u32(ZB_PTR(st, 0, kr, nc + 16)));
                ldsm4t(&b_l[4], smem_u32(ZB_PTR(st, 1, kr, nc + 16)));
            }
            #pragma unroll
            for (int mi = 0; mi < 4; mi++) {
                unsigned a_h[4], a_l[4];
                ldsm4(a_h, smem_u32(ZA_PTR(st, 0, wm + mi*16 + (lane & 15), kk + ((lane >> 4) << 3))));
                ldsm4(a_l, smem_u32(ZA_PTR(st, 1, wm + mi*16 + (lane & 15), kk + ((lane >> 4) << 3))));
                #pragma unroll
                for (int ni = 0; ni < 4; ni++) {
                    mma16(acc[mi][ni], a_h, &b_h[ni*2]);
                    mma16(acc[mi][ni], a_h, &b_l[ni*2]);
                    mma16(acc[mi][ni], a_l, &b_h[ni*2]);
                }
            }
        }
        __syncthreads();
    }

    // ---- fused octonion contraction epilogue (two 128-row halves) ----
    float* zs = (float*)dsm;                 // [128][132] staging
    const int g = lane >> 2, t4 = lane & 3;
    #pragma unroll 1
    for (int hh = 0; hh < 2; hh++) {
        __syncthreads();
        if ((warp >> 3) == hh) {
            const int lwm = wm - hh * 128;   // 0 or 64
            #pragma unroll
            for (int mi = 0; mi < 4; mi++)
                #pragma unroll
                for (int ni = 0; ni < 4; ni++) {
                    const int lr = lwm + mi * 16 + g;
                    const int c  = wn + ni * 8 + 2 * t4;
                    zs[lr * 132 + c]           = acc[mi][ni][0];
                    zs[lr * 132 + c + 1]       = acc[mi][ni][1];
                    zs[(lr + 8) * 132 + c]     = acc[mi][ni][2];
                    zs[(lr + 8) * 132 + c + 1] = acc[mi][ni][3];
                }
        }
        __syncthreads();
        if (tid < 256) {
            const int r   = tid >> 1, gg = tid & 1;
            const int row = m0 + hh * 128 + r;
            const int m   = (n0 >> 6) + gg;
            const float* u_ptr = qh + ((size_t)h * T_SEQ + row) * HD + m * 8;
            float u[8];
            #pragma unroll
            for (int i = 0; i < 8; i++) u[i] = u_ptr[i];
            const float* zr = zs + r * 132 + gg * 64;

            float y[8] = {};
            #pragma unroll
            for (int p = 0; p < 8; p++) {
                float ep[8] = {};
                ep[p] = 1.0f;
                float w[8];
                omul_d(u, ep, w);
                float zp[8];
                #pragma unroll
                for (int q = 0; q < 8; q++) zp[q] = zr[p * 8 + q];
                float tt[8];
                omul_d(w, zp, tt);
                #pragma unroll
                for (int k = 0; k < 8; k++) y[k] += tt[k];
            }
            const size_t ob = (size_t)row * NE + h * 64 + m * 8;
            #pragma unroll
            for (int k = 0; k < 8; k++) {
                bf16 hi, lo;
                split1(y[k], hi, lo);
                yph[ob + k] = hi;
                ypl[ob + k] = lo;
            }
        }
    }
}

// ---------------- fused RoPE + RMS + octonion conj-unit + KV outer ----------
__global__ __launch_bounds__(512) void rope_rms_kv(
    const float* __restrict__ qraw, const float* __restrict__ kraw,
    const float* __restrict__ vraw, const float* __restrict__ cosb,
    const float* __restrict__ sinb,
    float* __restrict__ qh,
    bf16* __restrict__ qhh, bf16* __restrict__ qhl,
    bf16* __restrict__ khh, bf16* __restrict__ khl,
    bf16* __restrict__ kvh, bf16* __restrict__ kvl)
{
    const int t = blockIdx.x;
    const int h = threadIdx.x >> 5;
    const int lane = threadIdx.x & 31;
    const unsigned FULL = 0xffffffffu;

    const float c = cosb[t * 32 + lane];
    const float s = sinb[t * 32 + lane];
    const size_t base = (size_t)t * NE + (size_t)h * HD;
    float q1 = qraw[base + lane], q2 = qraw[base + lane + 32];
    float k1 = kraw[base + lane], k2 = kraw[base + lane + 32];
    float v1 = vraw[base + lane], v2 = vraw[base + lane + 32];

    float qr1 = q1 * c + q2 * s, qr2 = q2 * c - q1 * s;
    float kr1 = k1 * c + k2 * s, kr2 = k2 * c - k1 * s;

    float sq = qr1 * qr1 + qr2 * qr2;
    float sk = kr1 * kr1 + kr2 * kr2;
    #pragma unroll
    for (int off = 16; off > 0; off >>= 1) {
        sq += __shfl_xor_sync(FULL, sq, off);
        sk += __shfl_xor_sync(FULL, sk, off);
    }
    const float rq = rsqrtf(sq * (1.0f / 64.0f) + 1e-6f);
    const float rk = rsqrtf(sk * (1.0f / 64.0f) + 1e-6f);
    qr1 *= rq; qr2 *= rq;
    kr1 *= rk; kr2 *= rk;

    const size_t hb = ((size_t)h * T_SEQ + t) * HD;
    qh[hb + lane] = qr1; qh[hb + lane + 32] = qr2;
    {
        bf16 hi, lo;
        split1(qr1, hi, lo); qhh[hb + lane] = hi;      qhl[hb + lane] = lo;
        split1(qr2, hi, lo); qhh[hb + lane + 32] = hi; qhl[hb + lane + 32] = lo;
        split1(kr1, hi, lo); khh[hb + lane] = hi;      khl[hb + lane] = lo;
        split1(kr2, hi, lo); khh[hb + lane + 32] = hi; khl[hb + lane + 32] = lo;
    }

    float g1 = kr1 * kr1, g2 = kr2 * kr2;
    #pragma unroll
    for (int off = 1; off < 8; off <<= 1) {
        g1 += __shfl_xor_sync(FULL, g1, off);
        g2 += __shfl_xor_sync(FULL, g2, off);
    }
    const float sgn = ((lane & 7) == 0) ? 1.0f : -1.0f;
    const float kc1 = sgn * kr1 / fmaxf(sqrtf(g1), 1e-12f);
    const float kc2 = sgn * kr2 / fmaxf(sqrtf(g2), 1e-12f);

    __shared__ float skc[16][64];
    __shared__ float sv[16][64];
    skc[h][lane] = kc1; skc[h][lane + 32] = kc2;
    sv[h][lane]  = v1;  sv[h][lane + 32]  = v2;
    __syncwarp();

    const size_t kvb = ((size_t)h * T_SEQ + t) * KVW;
    #pragma unroll
    for (int r = 0; r < 16; r++) {
        int n = lane + 32 * r;
        int m = n >> 6, p = (n >> 3) & 7, q = n & 7;
        float val = skc[h][m * 8 + p] * sv[h][m * 8 + q];
        bf16 hi, lo;
        split1(val, hi, lo);
        kvh[kvb + n] = hi;
        kvl[kvb + n] = lo;
    }
}

// ---------------- softmax rows -> bf16 hi/lo planes + 256-band zero-fill ----
__global__ __launch_bounds__(256) void softmax_rows(
    const float* __restrict__ att, bf16* __restrict__ atth, bf16* __restrict__ attl)
{
    const int i = blockIdx.x;
    const int h = blockIdx.y;
    const float* row = att + (size_t)h * T_SEQ * T_SEQ + (size_t)i * T_SEQ;
    bf16* rh = atth + (size_t)h * T_SEQ * T_SEQ + (size_t)i * T_SEQ;
    bf16* rl = attl + (size_t)h * T_SEQ * T_SEQ + (size_t)i * T_SEQ;
    const int n = i + 1;
    const int tid = threadIdx.x;

    float v[8];
    int cnt = 0;
    float mx = -1e30f;
    for (int j = tid; j < n; j += 256) {
        float x = row[j];
        v[cnt++] = x;
        mx = fmaxf(mx, x);
    }
    __shared__ float red[256];
    red[tid] = mx; __syncthreads();
    #pragma unroll
    for (int s = 128; s > 0; s >>= 1) {
        if (tid < s) red[tid] = fmaxf(red[tid], red[tid + s]);
        __syncthreads();
    }
    mx = red[0]; __syncthreads();

    float sum = 0.0f;
    for (int c2 = 0; c2 < cnt; c2++) { v[c2] = __expf(v[c2] - mx); sum += v[c2]; }
    red[tid] = sum; __syncthreads();
    #pragma unroll
    for (int s = 128; s > 0; s >>= 1) {
        if (tid < s) red[tid] += red[tid + s];
        __syncthreads();
    }
    const float inv = 1.0f / red[0];
    cnt = 0;
    for (int j = tid; j < n; j += 256) {
        float p = v[cnt++] * inv;
        bf16 hi, lo;
        split1(p, hi, lo);
        rh[j] = hi;
        rl[j] = lo;
    }
    // zero-fill to this row's 256-block boundary (bf_z reads K up to m0+256)
    const bf16 zb = __float2bfloat16(0.0f);
    const int mend = ((i >> 8) << 8) + 256;
    for (int j = i + 1 + tid; j < mend; j += 256) { rh[j] = zb; rl[j] = zb; }
}

// ---------------- launch ----------------------------------------------------
extern "C" void kernel_launch(void* const* d_in, const int* in_sizes, int n_in,
                              void* d_out, int out_size)
{
    const float* x    = (const float*)d_in[0];
    const float* cosb = (const float*)d_in[1];
    const float* sinb = (const float*)d_in[2];
    const float* Wq   = (const float*)d_in[3];
    const float* Wk   = (const float*)d_in[4];
    const float* Wv   = (const float*)d_in[5];
    const float* Wo   = (const float*)d_in[6];
    float* out = (float*)d_out;

    float *qraw, *kraw, *vraw, *qh, *att;
    bf16 *xh, *xl, *wqh, *wql, *wkh, *wkl, *wvh, *wvl, *woh, *wol;
    bf16 *qhh, *qhl, *khh, *khl, *kvh, *kvl, *atth, *attl, *yph, *ypl;
    cudaGetSymbolAddress((void**)&qraw, g_qraw);
    cudaGetSymbolAddress((void**)&kraw, g_kraw);
    cudaGetSymbolAddress((void**)&vraw, g_vraw);
    cudaGetSymbolAddress((void**)&qh,   g_qh);
    cudaGetSymbolAddress((void**)&att,  g_att);
    cudaGetSymbolAddress((void**)&xh,  g_xh);  cudaGetSymbolAddress((void**)&xl,  g_xl);
    cudaGetSymbolAddress((void**)&wqh, g_wqh); cudaGetSymbolAddress((void**)&wql, g_wql);
    cudaGetSymbolAddress((void**)&wkh, g_wkh); cudaGetSymbolAddress((void**)&wkl, g_wkl);
    cudaGetSymbolAddress((void**)&wvh, g_wvh); cudaGetSymbolAddress((void**)&wvl, g_wvl);
    cudaGetSymbolAddress((void**)&woh, g_woh); cudaGetSymbolAddress((void**)&wol, g_wol);
    cudaGetSymbolAddress((void**)&qhh, g_qhh); cudaGetSymbolAddress((void**)&qhl, g_qhl);
    cudaGetSymbolAddress((void**)&khh, g_khh); cudaGetSymbolAddress((void**)&khl, g_khl);
    cudaGetSymbolAddress((void**)&kvh, g_kvh); cudaGetSymbolAddress((void**)&kvl, g_kvl);
    cudaGetSymbolAddress((void**)&atth, g_atth); cudaGetSymbolAddress((void**)&attl, g_attl);
    cudaGetSymbolAddress((void**)&yph, g_yph); cudaGetSymbolAddress((void**)&ypl, g_ypl);

    const size_t sQK  = (size_t)T_SEQ * HD;
    const size_t sAtt = (size_t)T_SEQ * T_SEQ;

    // 0: split inputs / weights into bf16 hi/lo planes
    const int nx = T_SEQ * NE, nw = NE * NE;
    split_f32<<<(nx/2 + 255)/256, 256>>>(x,  xh,  xl,  nx);
    split_f32<<<(nw/2 + 255)/256, 256>>>(Wq, wqh, wql, nw);
    split_f32<<<(nw/2 + 255)/256, 256>>>(Wk, wkh, wkl, nw);
    split_f32<<<(nw/2 + 255)/256, 256>>>(Wv, wvh, wvl, nw);
    split_f32<<<(nw/2 + 255)/256, 256>>>(Wo, woh, wol, nw);

    // 1-3: QKV projections
    dim3 gproj(NE / 128, T_SEQ / 128, 1);
    bf_nt<<<gproj, 256>>>(xh, xl, wqh, wql, qraw, T_SEQ, NE, NE, 0, 0, 0, 1.0f, 0);
    bf_nt<<<gproj, 256>>>(xh, xl, wkh, wkl, kraw, T_SEQ, NE, NE, 0, 0, 0, 1.0f, 0);
    bf_nt<<<gproj, 256>>>(xh, xl, wvh, wvl, vraw, T_SEQ, NE, NE, 0, 0, 0, 1.0f, 0);

    // 4: rope + rms + octonion conj/unit + KV outer (writes bf16 planes)
    rope_rms_kv<<<T_SEQ, 512>>>(qraw, kraw, vraw, cosb, sinb,
                                qh, qhh, qhl, khh, khl, kvh, kvl);

    // 5: scores = (qh @ kh^T) / 8 per head, causal block-skip
    dim3 gsc(T_SEQ / 128, T_SEQ / 128, NH);
    bf_nt<<<gsc, 256>>>(qhh, qhl, khh, khl, att, T_SEQ, T_SEQ, HD, sQK, sQK, sAtt, 0.125f, 1);

    // 6: softmax -> bf16 hi/lo prob planes (+ 256-block causal zero-fill)
    softmax_rows<<<dim3(T_SEQ, NH), 256>>>(att, atth, attl);

    // 7: Z = probs @ KV + fused octonion contraction -> ypre bf16 planes
    cudaFuncSetAttribute(bf_z, cudaFuncAttributeMaxDynamicSharedMemorySize, ZSMEM);
    dim3 gz(KVW / 128, T_SEQ / 256, NH);
    bf_z<<<gz, 512, ZSMEM>>>(atth, attl, kvh, kvl, qh, yph, ypl);

    // 8: output projection
    dim3 gout(NE / 128, T_SEQ / 128, 1);
    bf_nt<<<gout, 256>>>(yph, ypl, woh, wol, out, T_SEQ, NE, NE, 0, 0, 0, 1.0f, 0);
}

// round 16
// speedup vs baseline: 2.8834x; 1.1086x over previous
#include <cuda_runtime.h>
#include <cuda_bf16.h>
#include <math.h>
#include <stdint.h>

#define T_SEQ 2048
#define NH 16
#define HD 64
#define NE 1024
#define KVW 512
#define NN (NE * NE)

typedef __nv_bfloat16 bf16;

// ---------------- scratch (static device globals) ---------------------------
__device__ float g_qkvraw[(size_t)3 * T_SEQ * NE];
__device__ float g_qh[(size_t)NH * T_SEQ * HD];      // fp32 for epilogue contraction
__device__ float g_gsum[(size_t)NH * T_SEQ];        // softmax row sums
__device__ bf16 g_xh[(size_t)T_SEQ * NE],  g_xl[(size_t)T_SEQ * NE];
__device__ bf16 g_wh[(size_t)3 * NN],      g_wl[(size_t)3 * NN];   // Wq|Wk|Wv planes
__device__ bf16 g_woh[(size_t)NN],         g_wol[(size_t)NN];
__device__ bf16 g_qhh[(size_t)NH * T_SEQ * HD],  g_qhl[(size_t)NH * T_SEQ * HD];
__device__ bf16 g_khh[(size_t)NH * T_SEQ * HD],  g_khl[(size_t)NH * T_SEQ * HD];
__device__ bf16 g_kvh[(size_t)NH * T_SEQ * KVW], g_kvl[(size_t)NH * T_SEQ * KVW];
__device__ bf16 g_eh[(size_t)NH * T_SEQ * T_SEQ], g_el[(size_t)NH * T_SEQ * T_SEQ];
__device__ bf16 g_yph[(size_t)T_SEQ * NE], g_ypl[(size_t)T_SEQ * NE];

// ---------------- helpers ----------------------------------------------------
__device__ __forceinline__ unsigned smem_u32(const void* p) {
    return (unsigned)__cvta_generic_to_shared(p);
}
#define CPA16(dst_u32, src_ptr) \
    asm volatile("cp.async.cg.shared.global [%0], [%1], 16;" :: "r"(dst_u32), "l"(src_ptr))
#define CPCOMMIT() asm volatile("cp.async.commit_group;")
#define CPWAIT2()  asm volatile("cp.async.wait_group 2;")
#define CPWAIT1()  asm volatile("cp.async.wait_group 1;")
#define CPWAIT0()  asm volatile("cp.async.wait_group 0;")

__device__ __forceinline__ void mma16(float* d, const unsigned* a, const unsigned* b) {
    asm volatile(
        "mma.sync.aligned.m16n8k16.row.col.f32.bf16.bf16.f32 "
        "{%0,%1,%2,%3},{%4,%5,%6,%7},{%8,%9},{%0,%1,%2,%3};"
        : "+f"(d[0]), "+f"(d[1]), "+f"(d[2]), "+f"(d[3])
        : "r"(a[0]), "r"(a[1]), "r"(a[2]), "r"(a[3]), "r"(b[0]), "r"(b[1]));
}
__device__ __forceinline__ void ldsm4(unsigned* r, unsigned a) {
    asm volatile("ldmatrix.sync.aligned.m8n8.x4.shared.b16 {%0,%1,%2,%3}, [%4];"
        : "=r"(r[0]), "=r"(r[1]), "=r"(r[2]), "=r"(r[3]) : "r"(a));
}
__device__ __forceinline__ void ldsm4t(unsigned* r, unsigned a) {
    asm volatile("ldmatrix.sync.aligned.m8n8.x4.trans.shared.b16 {%0,%1,%2,%3}, [%4];"
        : "=r"(r[0]), "=r"(r[1]), "=r"(r[2]), "=r"(r[3]) : "r"(a));
}
__device__ __forceinline__ void split2(float x0, float x1, unsigned& hi, unsigned& lo) {
    __nv_bfloat162 h = __floats2bfloat162_rn(x0, x1);
    hi = *reinterpret_cast<unsigned*>(&h);
    float2 hf = __bfloat1622float2(h);
    __nv_bfloat162 l = __floats2bfloat162_rn(x0 - hf.x, x1 - hf.y);
    lo = *reinterpret_cast<unsigned*>(&l);
}
__device__ __forceinline__ void split1(float x, bf16& hi, bf16& lo) {
    hi = __float2bfloat16(x);
    lo = __float2bfloat16(x - __bfloat162float(hi));
}

// ---------------- merged split kernel (x, Wq, Wk, Wv -> wh/wl slabs, Wo) ----
__global__ __launch_bounds__(256) void split_all(
    const float* __restrict__ x,  const float* __restrict__ Wq,
    const float* __restrict__ Wk, const float* __restrict__ Wv,
    const float* __restrict__ Wo,
    bf16* __restrict__ xh, bf16* __restrict__ xl,
    bf16* __restrict__ wh, bf16* __restrict__ wl,
    bf16* __restrict__ woh, bf16* __restrict__ wol)
{
    const int i = (blockIdx.x * 256 + threadIdx.x) * 2;   // elem index (pairs)
    const int nx = T_SEQ * NE;
    const float* s;
    bf16 *dh, *dl;
    int off;
    if (i < nx) { s = x; dh = xh; dl = xl; off = i; }
    else {
        int j = i - nx;
        int w = j >> 20;            // NN = 2^20
        int wi = j & (NN - 1);
        if (w < 3) { s = (w == 0) ? Wq : (w == 1) ? Wk : Wv; dh = wh + (size_t)w * NN; dl = wl + (size_t)w * NN; }
        else       { s = Wo; dh = woh; dl = wol; }
        off = wi;
    }
    float2 v = *(const float2*)&s[off];
    unsigned hh, ll;
    split2(v.x, v.y, hh, ll);
    *(unsigned*)&dh[off] = hh;
    *(unsigned*)&dl[off] = ll;
}

// ---------------- octonion helpers ------------------------------------------
__device__ __forceinline__ void qmul_d(const float* a, const float* b, float* r) {
    r[0] = a[0]*b[0] - a[1]*b[1] - a[2]*b[2] - a[3]*b[3];
    r[1] = a[0]*b[1] + a[1]*b[0] + a[2]*b[3] - a[3]*b[2];
    r[2] = a[0]*b[2] - a[1]*b[3] + a[2]*b[0] + a[3]*b[1];
    r[3] = a[0]*b[3] + a[1]*b[2] - a[2]*b[1] + a[3]*b[0];
}
__device__ __forceinline__ void omul_d(const float* x, const float* y, float* r) {
    float a[4] = {x[0], x[1], x[2], x[3]};
    float b[4] = {x[4], x[5], x[6], x[7]};
    float c[4] = {y[0], y[1], y[2], y[3]};
    float d[4] = {y[4], y[5], y[6], y[7]};
    float dc[4] = { d[0], -d[1], -d[2], -d[3] };
    float cc[4] = { c[0], -c[1], -c[2], -c[3] };
    float t1[4], t2[4], t3[4], t4[4];
    qmul_d(a,  c,  t1);
    qmul_d(dc, b,  t2);
    qmul_d(d,  a,  t3);
    qmul_d(b,  cc, t4);
    #pragma unroll
    for (int i = 0; i < 4; i++) { r[i]   = t1[i] - t2[i]; }
    #pragma unroll
    for (int i = 0; i < 4; i++) { r[4+i] = t3[i] + t4[i]; }
}

// ============================================================================
// bf16-plane legacy MMA GEMM (NT): C = alpha * (Ah+Al) @ (Bh+Bl)^T
// BM=128, BN=128, BK=32, 256 threads (8 warps 4m x 2n), warp tile 32x64.
// ============================================================================
__global__ __launch_bounds__(256) void bf_nt(
    const bf16* __restrict__ Ah, const bf16* __restrict__ Al,
    const bf16* __restrict__ Bh, const bf16* __restrict__ Bl,
    float* __restrict__ C,
    int M, int N, int K, size_t sA, size_t sB, size_t sC, float alpha)
{
    const int m0 = blockIdx.y * 128;
    const int n0 = blockIdx.x * 128;
    Ah += (size_t)blockIdx.z * sA;  Al += (size_t)blockIdx.z * sA;
    Bh += (size_t)blockIdx.z * sB;  Bl += (size_t)blockIdx.z * sB;
    C  += (size_t)blockIdx.z * sC;

    __shared__ __align__(16) bf16 As[2][2][128][40];
    __shared__ __align__(16) bf16 Bs[2][2][128][40];

    const int tid  = threadIdx.x;
    const int warp = tid >> 5, lane = tid & 31;
    const int wm = (warp >> 1) * 32, wn = (warp & 1) * 64;

    const int arow = tid >> 2;
    const int akc  = (tid & 3) * 8;

    float acc[2][8][4] = {};

    const bf16* Ap[2] = {Ah, Al};
    const bf16* Bp[2] = {Bh, Bl};

    #pragma unroll
    for (int p = 0; p < 2; p++) {
        CPA16(smem_u32(&As[0][p][arow][akc]),      &Ap[p][(size_t)(m0 + arow)      * K + akc]);
        CPA16(smem_u32(&As[0][p][arow + 64][akc]), &Ap[p][(size_t)(m0 + arow + 64) * K + akc]);
        CPA16(smem_u32(&Bs[0][p][arow][akc]),      &Bp[p][(size_t)(n0 + arow)      * K + akc]);
        CPA16(smem_u32(&Bs[0][p][arow + 64][akc]), &Bp[p][(size_t)(n0 + arow + 64) * K + akc]);
    }
    CPCOMMIT();

    int buf = 0;
    for (int k0 = 0; k0 < K; k0 += 32) {
        if (k0 + 32 < K) {
            const int kn = k0 + 32;
            #pragma unroll
            for (int p = 0; p < 2; p++) {
                CPA16(smem_u32(&As[buf ^ 1][p][arow][akc]),      &Ap[p][(size_t)(m0 + arow)      * K + kn + akc]);
                CPA16(smem_u32(&As[buf ^ 1][p][arow + 64][akc]), &Ap[p][(size_t)(m0 + arow + 64) * K + kn + akc]);
                CPA16(smem_u32(&Bs[buf ^ 1][p][arow][akc]),      &Bp[p][(size_t)(n0 + arow)      * K + kn + akc]);
                CPA16(smem_u32(&Bs[buf ^ 1][p][arow + 64][akc]), &Bp[p][(size_t)(n0 + arow + 64) * K + kn + akc]);
            }
            CPCOMMIT();
            CPWAIT1();
        } else {
            CPWAIT0();
        }
        __syncthreads();

        #pragma unroll
        for (int kk = 0; kk < 32; kk += 16) {
            unsigned b_h[16], b_l[16];
            {
                const int br = wn + (lane & 7) + ((lane >> 4) << 3);
                const int bc = kk + (((lane >> 3) & 1) << 3);
                ldsm4(&b_h[0],  smem_u32(&Bs[buf][0][br][bc]));
                ldsm4(&b_l[0],  smem_u32(&Bs[buf][1][br][bc]));
                ldsm4(&b_h[4],  smem_u32(&Bs[buf][0][br + 16][bc]));
                ldsm4(&b_l[4],  smem_u32(&Bs[buf][1][br + 16][bc]));
                ldsm4(&b_h[8],  smem_u32(&Bs[buf][0][br + 32][bc]));
                ldsm4(&b_l[8],  smem_u32(&Bs[buf][1][br + 32][bc]));
                ldsm4(&b_h[12], smem_u32(&Bs[buf][0][br + 48][bc]));
                ldsm4(&b_l[12], smem_u32(&Bs[buf][1][br + 48][bc]));
            }
            #pragma unroll
            for (int mi = 0; mi < 2; mi++) {
                unsigned a_h[4], a_l[4];
                ldsm4(a_h, smem_u32(&As[buf][0][wm + mi*16 + (lane & 15)][kk + ((lane >> 4) << 3)]));
                ldsm4(a_l, smem_u32(&As[buf][1][wm + mi*16 + (lane & 15)][kk + ((lane >> 4) << 3)]));
                #pragma unroll
                for (int ni = 0; ni < 8; ni++) {
                    mma16(acc[mi][ni], a_h, &b_h[ni*2]);
                    mma16(acc[mi][ni], a_h, &b_l[ni*2]);
                    mma16(acc[mi][ni], a_l, &b_h[ni*2]);
                }
            }
        }
        __syncthreads();
        buf ^= 1;
    }

    const int g = lane >> 2, t = lane & 3;
    #pragma unroll
    for (int mi = 0; mi < 2; mi++)
        #pragma unroll
        for (int ni = 0; ni < 8; ni++) {
            const int row = m0 + wm + mi * 16 + g;
            const int col = n0 + wn + ni * 8 + 2 * t;
            float2 v0 = make_float2(alpha * acc[mi][ni][0], alpha * acc[mi][ni][1]);
            float2 v1 = make_float2(alpha * acc[mi][ni][2], alpha * acc[mi][ni][3]);
            *(float2*)&C[(size_t)row * N + col]       = v0;
            *(float2*)&C[(size_t)(row + 8) * N + col] = v1;
        }
}

// ============================================================================
// scores GEMM + fused exp + row-sum atomics.
// e[i][j] = exp(q_i . k_j / 8) for j<=i else 0; writes bf16 hi/lo planes and
// atomically accumulates gsum[h][i] = sum_j e[i][j].
// Same tiling as bf_nt, K=HD=64. Tiles with n0 > m0+255 skipped (bf_z never
// reads them); tiles in (m0+127, m0+255] band are fully masked -> zeros.
// ============================================================================
__global__ __launch_bounds__(256) void bf_scores(
    const bf16* __restrict__ qhh, const bf16* __restrict__ qhl,
    const bf16* __restrict__ khh, const bf16* __restrict__ khl,
    bf16* __restrict__ ehp, bf16* __restrict__ elp, float* __restrict__ gsum)
{
    const int m0 = blockIdx.y * 128;
    const int n0 = blockIdx.x * 128;
    if (n0 > m0 + 255) return;
    const int h = blockIdx.z;
    const bf16* Ap[2] = { qhh + (size_t)h * T_SEQ * HD, qhl + (size_t)h * T_SEQ * HD };
    const bf16* Bp[2] = { khh + (size_t)h * T_SEQ * HD, khl + (size_t)h * T_SEQ * HD };
    bf16* eh = ehp + (size_t)h * T_SEQ * T_SEQ;
    bf16* el = elp + (size_t)h * T_SEQ * T_SEQ;
    float* gs = gsum + (size_t)h * T_SEQ;

    __shared__ __align__(16) bf16 As[2][2][128][40];
    __shared__ __align__(16) bf16 Bs[2][2][128][40];

    const int tid  = threadIdx.x;
    const int warp = tid >> 5, lane = tid & 31;
    const int wm = (warp >> 1) * 32, wn = (warp & 1) * 64;
    const int arow = tid >> 2;
    const int akc  = (tid & 3) * 8;

    float acc[2][8][4] = {};

    #pragma unroll
    for (int p = 0; p < 2; p++) {
        CPA16(smem_u32(&As[0][p][arow][akc]),      &Ap[p][(size_t)(m0 + arow)      * HD + akc]);
        CPA16(smem_u32(&As[0][p][arow + 64][akc]), &Ap[p][(size_t)(m0 + arow + 64) * HD + akc]);
        CPA16(smem_u32(&Bs[0][p][arow][akc]),      &Bp[p][(size_t)(n0 + arow)      * HD + akc]);
        CPA16(smem_u32(&Bs[0][p][arow + 64][akc]), &Bp[p][(size_t)(n0 + arow + 64) * HD + akc]);
    }
    CPCOMMIT();

    int buf = 0;
    for (int k0 = 0; k0 < HD; k0 += 32) {
        if (k0 + 32 < HD) {
            const int kn = k0 + 32;
            #pragma unroll
            for (int p = 0; p < 2; p++) {
                CPA16(smem_u32(&As[buf ^ 1][p][arow][akc]),      &Ap[p][(size_t)(m0 + arow)      * HD + kn + akc]);
                CPA16(smem_u32(&As[buf ^ 1][p][arow + 64][akc]), &Ap[p][(size_t)(m0 + arow + 64) * HD + kn + akc]);
                CPA16(smem_u32(&Bs[buf ^ 1][p][arow][akc]),      &Bp[p][(size_t)(n0 + arow)      * HD + kn + akc]);
                CPA16(smem_u32(&Bs[buf ^ 1][p][arow + 64][akc]), &Bp[p][(size_t)(n0 + arow + 64) * HD + kn + akc]);
            }
            CPCOMMIT();
            CPWAIT1();
        } else {
            CPWAIT0();
        }
        __syncthreads();

        #pragma unroll
        for (int kk = 0; kk < 32; kk += 16) {
            unsigned b_h[16], b_l[16];
            {
                const int br = wn + (lane & 7) + ((lane >> 4) << 3);
                const int bc = kk + (((lane >> 3) & 1) << 3);
                ldsm4(&b_h[0],  smem_u32(&Bs[buf][0][br][bc]));
                ldsm4(&b_l[0],  smem_u32(&Bs[buf][1][br][bc]));
                ldsm4(&b_h[4],  smem_u32(&Bs[buf][0][br + 16][bc]));
                ldsm4(&b_l[4],  smem_u32(&Bs[buf][1][br + 16][bc]));
                ldsm4(&b_h[8],  smem_u32(&Bs[buf][0][br + 32][bc]));
                ldsm4(&b_l[8],  smem_u32(&Bs[buf][1][br + 32][bc]));
                ldsm4(&b_h[12], smem_u32(&Bs[buf][0][br + 48][bc]));
                ldsm4(&b_l[12], smem_u32(&Bs[buf][1][br + 48][bc]));
            }
            #pragma unroll
            for (int mi = 0; mi < 2; mi++) {
                unsigned a_h[4], a_l[4];
                ldsm4(a_h, smem_u32(&As[buf][0][wm + mi*16 + (lane & 15)][kk + ((lane >> 4) << 3)]));
                ldsm4(a_l, smem_u32(&As[buf][1][wm + mi*16 + (lane & 15)][kk + ((lane >> 4) << 3)]));
                #pragma unroll
                for (int ni = 0; ni < 8; ni++) {
                    mma16(acc[mi][ni], a_h, &b_h[ni*2]);
                    mma16(acc[mi][ni], a_h, &b_l[ni*2]);
                    mma16(acc[mi][ni], a_l, &b_h[ni*2]);
                }
            }
        }
        __syncthreads();
        buf ^= 1;
    }

    // epilogue: exp + causal mask + bf16 hi/lo store + row-sum atomics
    const int g = lane >> 2, t = lane & 3;
    #pragma unroll
    for (int mi = 0; mi < 2; mi++) {
        const int r0 = m0 + wm + mi * 16 + g;
        float ps0 = 0.0f, ps1 = 0.0f;
        #pragma unroll
        for (int ni = 0; ni < 8; ni++) {
            const int col = n0 + wn + ni * 8 + 2 * t;
            float e00 = (col     <= r0)     ? __expf(acc[mi][ni][0] * 0.125f) : 0.0f;
            float e01 = (col + 1 <= r0)     ? __expf(acc[mi][ni][1] * 0.125f) : 0.0f;
            float e10 = (col     <= r0 + 8) ? __expf(acc[mi][ni][2] * 0.125f) : 0.0f;
            float e11 = (col + 1 <= r0 + 8) ? __expf(acc[mi][ni][3] * 0.125f) : 0.0f;
            unsigned hh, ll;
            split2(e00, e01, hh, ll);
            *(unsigned*)&eh[(size_t)r0 * T_SEQ + col] = hh;
            *(unsigned*)&el[(size_t)r0 * T_SEQ + col] = ll;
            split2(e10, e11, hh, ll);
            *(unsigned*)&eh[(size_t)(r0 + 8) * T_SEQ + col] = hh;
            *(unsigned*)&el[(size_t)(r0 + 8) * T_SEQ + col] = ll;
            ps0 += e00 + e01;
            ps1 += e10 + e11;
        }
        #pragma unroll
        for (int off = 1; off < 4; off <<= 1) {
            ps0 += __shfl_xor_sync(0xffffffffu, ps0, off);
            ps1 += __shfl_xor_sync(0xffffffffu, ps1, off);
        }
        if (t == 0) {
            atomicAdd(&gs[r0],     ps0);
            atomicAdd(&gs[r0 + 8], ps1);
        }
    }
}

// ============================================================================
// z-GEMM on exp planes + fused 1/rowsum scaling + octonion contraction.
// BM=256, BN=128, BK=32, 512 threads (16 warps 4m x 4n), warp tile 64x32.
// 3-stage cp.async pipeline, dynamic smem.
// ============================================================================
#define ZA_STRIDE 40
#define ZB_STRIDE 136
#define ZA_BYTES (256 * ZA_STRIDE * 2)
#define ZB_BASE  (6 * ZA_BYTES)
#define ZB_BYTES (32 * ZB_STRIDE * 2)
#define ZSMEM    (ZB_BASE + 6 * ZB_BYTES)

__global__ void __launch_bounds__(512) bf_z(
    const bf16* __restrict__ Ahh, const bf16* __restrict__ All,
    const bf16* __restrict__ Bhh, const bf16* __restrict__ Bll,
    const float* __restrict__ qh, const float* __restrict__ gsum,
    bf16* __restrict__ yph, bf16* __restrict__ ypl)
{
    extern __shared__ __align__(16) char dsm[];
    const int h  = blockIdx.z;
    const int m0 = blockIdx.y * 256;
    const int n0 = blockIdx.x * 128;
    const bf16* Ap[2] = { Ahh + (size_t)h * T_SEQ * T_SEQ, All + (size_t)h * T_SEQ * T_SEQ };
    const bf16* Bp[2] = { Bhh + (size_t)h * T_SEQ * KVW,  Bll + (size_t)h * T_SEQ * KVW };
    const int nk = m0 / 32 + 8;

    const int tid  = threadIdx.x;
    const int warp = tid >> 5, lane = tid & 31;
    const int wm = (warp >> 2) * 64, wn = (warp & 3) * 32;

    const int arow = tid >> 2;
    const int akc  = (tid & 3) * 8;
    const int bkr  = tid >> 4;
    const int bnc  = (tid & 15) * 8;

    float acc[4][4][4] = {};

    #define ZA_PTR(s, p, r, c) ((bf16*)(dsm + ((s) * 2 + (p)) * ZA_BYTES) + (r) * ZA_STRIDE + (c))
    #define ZB_PTR(s, p, r, c) ((bf16*)(dsm + ZB_BASE + ((s) * 2 + (p)) * ZB_BYTES) + (r) * ZB_STRIDE + (c))

    auto load_stage = [&](int s, int k0) {
        #pragma unroll
        for (int p = 0; p < 2; p++) {
            CPA16(smem_u32(ZA_PTR(s, p, arow, akc)),       &Ap[p][(size_t)(m0 + arow)       * T_SEQ + k0 + akc]);
            CPA16(smem_u32(ZA_PTR(s, p, arow + 128, akc)), &Ap[p][(size_t)(m0 + arow + 128) * T_SEQ + k0 + akc]);
            CPA16(smem_u32(ZB_PTR(s, p, bkr, bnc)),        &Bp[p][(size_t)(k0 + bkr) * KVW + n0 + bnc]);
        }
    };

    load_stage(0, 0);  CPCOMMIT();
    load_stage(1, 32); CPCOMMIT();

    for (int kt = 0; kt < nk; kt++) {
        const int st = kt % 3;
        if (kt + 2 < nk) load_stage((kt + 2) % 3, (kt + 2) * 32);
        CPCOMMIT();
        CPWAIT2();
        __syncthreads();

        #pragma unroll
        for (int kk = 0; kk < 32; kk += 16) {
            unsigned b_h[8], b_l[8];
            {
                const int kr = kk + (lane & 7) + (((lane >> 3) & 1) << 3);
                const int nc = wn + ((lane >> 4) << 3);
                ldsm4t(&b_h[0], smem_u32(ZB_PTR(st, 0, kr, nc)));
                ldsm4t(&b_l[0], smem_u32(ZB_PTR(st, 1, kr, nc)));
                ldsm4t(&b_h[4], smem_u32(ZB_PTR(st, 0, kr, nc + 16)));
                ldsm4t(&b_l[4], smem_u32(ZB_PTR(st, 1, kr, nc + 16)));
            }
            #pragma unroll
            for (int mi = 0; mi < 4; mi++) {
                unsigned a_h[4], a_l[4];
                ldsm4(a_h, smem_u32(ZA_PTR(st, 0, wm + mi*16 + (lane & 15), kk + ((lane >> 4) << 3))));
                ldsm4(a_l, smem_u32(ZA_PTR(st, 1, wm + mi*16 + (lane & 15), kk + ((lane >> 4) << 3))));
                #pragma unroll
                for (int ni = 0; ni < 4; ni++) {
                    mma16(acc[mi][ni], a_h, &b_h[ni*2]);
                    mma16(acc[mi][ni], a_h, &b_l[ni*2]);
                    mma16(acc[mi][ni], a_l, &b_h[ni*2]);
                }
            }
        }
        __syncthreads();
    }

    // ---- fused epilogue: stage acc -> smem, scale by 1/rowsum, contract ----
    float* zs = (float*)dsm;                 // [128][132] staging
    const int g = lane >> 2, t4 = lane & 3;
    #pragma unroll 1
    for (int hh = 0; hh < 2; hh++) {
        __syncthreads();
        if ((warp >> 3) == hh) {
            const int lwm = wm - hh * 128;
            #pragma unroll
            for (int mi = 0; mi < 4; mi++)
                #pragma unroll
                for (int ni = 0; ni < 4; ni++) {
                    const int lr = lwm + mi * 16 + g;
                    const int c  = wn + ni * 8 + 2 * t4;
                    zs[lr * 132 + c]           = acc[mi][ni][0];
                    zs[lr * 132 + c + 1]       = acc[mi][ni][1];
                    zs[(lr + 8) * 132 + c]     = acc[mi][ni][2];
                    zs[(lr + 8) * 132 + c + 1] = acc[mi][ni][3];
                }
        }
        __syncthreads();
        if (tid < 256) {
            const int r   = tid >> 1, gg = tid & 1;
            const int row = m0 + hh * 128 + r;
            const int m   = (n0 >> 6) + gg;
            const float sinv = 1.0f / gsum[(size_t)h * T_SEQ + row];
            const float* u_ptr = qh + ((size_t)h * T_SEQ + row) * HD + m * 8;
            float u[8];
            #pragma unroll
            for (int i = 0; i < 8; i++) u[i] = u_ptr[i];
            const float* zr = zs + r * 132 + gg * 64;

            float y[8] = {};
            #pragma unroll
            for (int p = 0; p < 8; p++) {
                float ep[8] = {};
                ep[p] = 1.0f;
                float w[8];
                omul_d(u, ep, w);
                float zp[8];
                #pragma unroll
                for (int q = 0; q < 8; q++) zp[q] = zr[p * 8 + q];
                float tt[8];
                omul_d(w, zp, tt);
                #pragma unroll
                for (int k = 0; k < 8; k++) y[k] += tt[k];
            }
            const size_t ob = (size_t)row * NE + h * 64 + m * 8;
            #pragma unroll
            for (int k = 0; k < 8; k++) {
                bf16 hi, lo;
                split1(y[k] * sinv, hi, lo);
                yph[ob + k] = hi;
                ypl[ob + k] = lo;
            }
        }
    }
}

// ---------------- fused RoPE + RMS + octonion conj-unit + KV outer ----------
__global__ __launch_bounds__(512) void rope_rms_kv(
    const float* __restrict__ qraw, const float* __restrict__ kraw,
    const float* __restrict__ vraw, const float* __restrict__ cosb,
    const float* __restrict__ sinb,
    float* __restrict__ qh,
    bf16* __restrict__ qhh, bf16* __restrict__ qhl,
    bf16* __restrict__ khh, bf16* __restrict__ khl,
    bf16* __restrict__ kvh, bf16* __restrict__ kvl)
{
    const int t = blockIdx.x;
    const int h = threadIdx.x >> 5;
    const int lane = threadIdx.x & 31;
    const unsigned FULL = 0xffffffffu;

    const float c = cosb[t * 32 + lane];
    const float s = sinb[t * 32 + lane];
    const size_t base = (size_t)t * NE + (size_t)h * HD;
    float q1 = qraw[base + lane], q2 = qraw[base + lane + 32];
    float k1 = kraw[base + lane], k2 = kraw[base + lane + 32];
    float v1 = vraw[base + lane], v2 = vraw[base + lane + 32];

    float qr1 = q1 * c + q2 * s, qr2 = q2 * c - q1 * s;
    float kr1 = k1 * c + k2 * s, kr2 = k2 * c - k1 * s;

    float sq = qr1 * qr1 + qr2 * qr2;
    float sk = kr1 * kr1 + kr2 * kr2;
    #pragma unroll
    for (int off = 16; off > 0; off >>= 1) {
        sq += __shfl_xor_sync(FULL, sq, off);
        sk += __shfl_xor_sync(FULL, sk, off);
    }
    const float rq = rsqrtf(sq * (1.0f / 64.0f) + 1e-6f);
    const float rk = rsqrtf(sk * (1.0f / 64.0f) + 1e-6f);
    qr1 *= rq; qr2 *= rq;
    kr1 *= rk; kr2 *= rk;

    const size_t hb = ((size_t)h * T_SEQ + t) * HD;
    qh[hb + lane] = qr1; qh[hb + lane + 32] = qr2;
    {
        bf16 hi, lo;
        split1(qr1, hi, lo); qhh[hb + lane] = hi;      qhl[hb + lane] = lo;
        split1(qr2, hi, lo); qhh[hb + lane + 32] = hi; qhl[hb + lane + 32] = lo;
        split1(kr1, hi, lo); khh[hb + lane] = hi;      khl[hb + lane] = lo;
        split1(kr2, hi, lo); khh[hb + lane + 32] = hi; khl[hb + lane + 32] = lo;
    }

    float g1 = kr1 * kr1, g2 = kr2 * kr2;
    #pragma unroll
    for (int off = 1; off < 8; off <<= 1) {
        g1 += __shfl_xor_sync(FULL, g1, off);
        g2 += __shfl_xor_sync(FULL, g2, off);
    }
    const float sgn = ((lane & 7) == 0) ? 1.0f : -1.0f;
    const float kc1 = sgn * kr1 / fmaxf(sqrtf(g1), 1e-12f);
    const float kc2 = sgn * kr2 / fmaxf(sqrtf(g2), 1e-12f);

    __shared__ float skc[16][64];
    __shared__ float sv[16][64];
    skc[h][lane] = kc1; skc[h][lane + 32] = kc2;
    sv[h][lane]  = v1;  sv[h][lane + 32]  = v2;
    __syncwarp();

    const size_t kvb = ((size_t)h * T_SEQ + t) * KVW;
    #pragma unroll
    for (int r = 0; r < 16; r++) {
        int n = lane + 32 * r;
        int m = n >> 6, p = (n >> 3) & 7, q = n & 7;
        float val = skc[h][m * 8 + p] * sv[h][m * 8 + q];
        bf16 hi, lo;
        split1(val, hi, lo);
        kvh[kvb + n] = hi;
        kvl[kvb + n] = lo;
    }
}

// ---------------- launch ----------------------------------------------------
extern "C" void kernel_launch(void* const* d_in, const int* in_sizes, int n_in,
                              void* d_out, int out_size)
{
    const float* x    = (const float*)d_in[0];
    const float* cosb = (const float*)d_in[1];
    const float* sinb = (const float*)d_in[2];
    const float* Wq   = (const float*)d_in[3];
    const float* Wk   = (const float*)d_in[4];
    const float* Wv   = (const float*)d_in[5];
    const float* Wo   = (const float*)d_in[6];
    float* out = (float*)d_out;

    float *qkvraw, *qh, *gsum;
    bf16 *xh, *xl, *wh, *wl, *woh, *wol;
    bf16 *qhh, *qhl, *khh, *khl, *kvh, *kvl, *eh, *el, *yph, *ypl;
    cudaGetSymbolAddress((void**)&qkvraw, g_qkvraw);
    cudaGetSymbolAddress((void**)&qh,   g_qh);
    cudaGetSymbolAddress((void**)&gsum, g_gsum);
    cudaGetSymbolAddress((void**)&xh,  g_xh);  cudaGetSymbolAddress((void**)&xl,  g_xl);
    cudaGetSymbolAddress((void**)&wh,  g_wh);  cudaGetSymbolAddress((void**)&wl,  g_wl);
    cudaGetSymbolAddress((void**)&woh, g_woh); cudaGetSymbolAddress((void**)&wol, g_wol);
    cudaGetSymbolAddress((void**)&qhh, g_qhh); cudaGetSymbolAddress((void**)&qhl, g_qhl);
    cudaGetSymbolAddress((void**)&khh, g_khh); cudaGetSymbolAddress((void**)&khl, g_khl);
    cudaGetSymbolAddress((void**)&kvh, g_kvh); cudaGetSymbolAddress((void**)&kvl, g_kvl);
    cudaGetSymbolAddress((void**)&eh,  g_eh);  cudaGetSymbolAddress((void**)&el,  g_el);
    cudaGetSymbolAddress((void**)&yph, g_yph); cudaGetSymbolAddress((void**)&ypl, g_ypl);

    // 0a: zero softmax row-sum accumulators (graph-replayed each call)
    cudaMemsetAsync(gsum, 0, (size_t)NH * T_SEQ * sizeof(float));

    // 0b: split all inputs/weights into bf16 hi/lo planes (one launch)
    const int total_pairs = (T_SEQ * NE + 4 * NN) / 2;
    split_all<<<(total_pairs + 255) / 256, 256>>>(x, Wq, Wk, Wv, Wo,
                                                  xh, xl, wh, wl, woh, wol);

    // 1: QKV projections (single stride-batched launch, z = 0,1,2)
    dim3 gproj(NE / 128, T_SEQ / 128, 3);
    bf_nt<<<gproj, 256>>>(xh, xl, wh, wl, qkvraw,
                          T_SEQ, NE, NE, 0, (size_t)NN, (size_t)T_SEQ * NE, 1.0f);

    // 2: rope + rms + octonion conj/unit + KV outer
    const float* qraw = qkvraw;
    const float* kraw = qkvraw + (size_t)T_SEQ * NE;
    const float* vraw = qkvraw + (size_t)2 * T_SEQ * NE;
    rope_rms_kv<<<T_SEQ, 512>>>(qraw, kraw, vraw, cosb, sinb,
                                qh, qhh, qhl, khh, khl, kvh, kvl);

    // 3: scores + exp + row sums (fused; no fp32 att, no softmax kernel)
    dim3 gsc(T_SEQ / 128, T_SEQ / 128, NH);
    bf_scores<<<gsc, 256>>>(qhh, qhl, khh, khl, eh, el, gsum);

    // 4: Z = e @ KV + 1/rowsum scaling + fused octonion contraction
    cudaFuncSetAttribute(bf_z, cudaFuncAttributeMaxDynamicSharedMemorySize, ZSMEM);
    dim3 gz(KVW / 128, T_SEQ / 256, NH);
    bf_z<<<gz, 512, ZSMEM>>>(eh, el, kvh, kvl, qh, gsum, yph, ypl);

    // 5: output projection
    dim3 gout(NE / 128, T_SEQ / 128, 1);
    bf_nt<<<gout, 256>>>(yph, ypl, woh, wol, out, T_SEQ, NE, NE, 0, 0, 0, 1.0f);
}